// round 1
// baseline (speedup 1.0000x reference)
#include <cuda_runtime.h>
#include <cuda_bf16.h>
#include <math.h>

// Problem constants
#define S_LEN 2048
#define HIDDEN 2560
#define NH 32
#define NKV 8
#define HD 128
#define QDIM (NH*HD)    // 4096
#define KVDIM (NKV*HD)  // 1024
#define GS 128

// -------- scratch (static device arrays; no allocation allowed) --------
__device__ float g_q[S_LEN * QDIM];   // 33.5 MB
__device__ float g_k[S_LEN * KVDIM];  // 8.4 MB
__device__ float g_v[S_LEN * KVDIM];  // 8.4 MB
__device__ float g_a[S_LEN * QDIM];   // 33.5 MB

// ======================================================================
// Dequant-fused SGEMM:  C[M,N] = A[M,K] @ W[K,N] (+bias)
// W[k][n] = ((qw[k/8][n] >> 4*(k%8)) & 15 - qz[k/128][n]) * sc[k/128][n]
// BM=128 BN=128 BK=8, 256 threads, 8x8 micro-tile
// ======================================================================
#define BM 128
#define BN 128
#define BK 8

__global__ __launch_bounds__(256)
void gemm_q4_kernel(const float* __restrict__ A,
                    const int*   __restrict__ qw,
                    const float* __restrict__ sc,
                    const int*   __restrict__ qz,
                    const float* __restrict__ bias,
                    float* __restrict__ C,
                    int M, int N, int K)
{
    __shared__ float As[BK][BM + 4];
    __shared__ float Bs[BK][BN];

    int tid = threadIdx.x;
    int bm = blockIdx.y * BM;
    int bn = blockIdx.x * BN;
    int tx = tid & 15;
    int ty = tid >> 4;

    int arow = tid >> 1;
    int acol = (tid & 1) << 2;

    float acc[8][8];
#pragma unroll
    for (int i = 0; i < 8; i++)
#pragma unroll
        for (int j = 0; j < 8; j++) acc[i][j] = 0.f;

    for (int k0 = 0; k0 < K; k0 += BK) {
        // --- load A tile (128x8) as float4 per thread ---
        float4 av = *(const float4*)(A + (size_t)(bm + arow) * K + k0 + acol);
        As[acol + 0][arow] = av.x;
        As[acol + 1][arow] = av.y;
        As[acol + 2][arow] = av.z;
        As[acol + 3][arow] = av.w;
        // --- dequant + load B tile (8x128): one packed int32 per n ---
        if (tid < BN) {
            int n = bn + tid;
            unsigned q = (unsigned)qw[(size_t)(k0 >> 3) * N + n];
            int g = k0 >> 7;
            float z = (float)qz[(size_t)g * N + n];
            float s = sc[(size_t)g * N + n];
#pragma unroll
            for (int j = 0; j < 8; j++)
                Bs[j][tid] = ((float)((q >> (4 * j)) & 15u) - z) * s;
        }
        __syncthreads();

#pragma unroll
        for (int kk = 0; kk < BK; kk++) {
            float4 a0 = *(const float4*)&As[kk][ty * 8];
            float4 a1 = *(const float4*)&As[kk][ty * 8 + 4];
            float4 b0 = *(const float4*)&Bs[kk][tx * 8];
            float4 b1 = *(const float4*)&Bs[kk][tx * 8 + 4];
            float af[8] = {a0.x, a0.y, a0.z, a0.w, a1.x, a1.y, a1.z, a1.w};
            float bf[8] = {b0.x, b0.y, b0.z, b0.w, b1.x, b1.y, b1.z, b1.w};
#pragma unroll
            for (int i = 0; i < 8; i++)
#pragma unroll
                for (int j = 0; j < 8; j++)
                    acc[i][j] += af[i] * bf[j];
        }
        __syncthreads();
    }

#pragma unroll
    for (int i = 0; i < 8; i++) {
        int m = bm + ty * 8 + i;
#pragma unroll
        for (int j = 0; j < 8; j += 4) {
            int n = bn + tx * 8 + j;
            float4 v = make_float4(acc[i][j], acc[i][j + 1], acc[i][j + 2], acc[i][j + 3]);
            if (bias) {
                v.x += bias[n];     v.y += bias[n + 1];
                v.z += bias[n + 2]; v.w += bias[n + 3];
            }
            *(float4*)(C + (size_t)m * N + n) = v;
        }
    }
}

// ======================================================================
// RoPE (in-place). blockIdx.x: head 0..39 (0..31 Q, 32..39 K), blockIdx.y: s
// ======================================================================
__global__ void rope_kernel(float* __restrict__ Qb, float* __restrict__ Kb,
                            const float* __restrict__ cosb,
                            const float* __restrict__ sinb)
{
    int s = blockIdx.y;
    int h = blockIdx.x;
    int d = threadIdx.x;  // 0..63
    float c1 = cosb[s * HD + d];
    float s1 = sinb[s * HD + d];
    float c2 = cosb[s * HD + d + 64];
    float s2 = sinb[s * HD + d + 64];
    float* base = (h < NH) ? (Qb + (size_t)s * QDIM + h * HD)
                           : (Kb + (size_t)s * KVDIM + (h - NH) * HD);
    float x1 = base[d];
    float x2 = base[d + 64];
    base[d]      = x1 * c1 - x2 * s1;
    base[d + 64] = x2 * c2 + x1 * s2;
}

// ======================================================================
// Flash attention, fp32, causal, GQA (4 Q-heads per KV head)
// BQ=64, BKT=64. 256 threads: tx 0..15 (k / dcols), ty 0..15 (q rows)
// per-thread: 4x4 score micro-tile, 4x8 output micro-tile
// ======================================================================
#define BQ 64
#define BKT 64
#define SQ 132   // Qs row stride (pad)
#define SKS 129  // Ks row stride
#define SV 132   // Vs row stride
#define SP 65    // Ps row stride

__global__ __launch_bounds__(256)
void flash_kernel(const float* __restrict__ Q,
                  const float* __restrict__ Kb,
                  const float* __restrict__ Vb,
                  float* __restrict__ O)
{
    extern __shared__ float sm[];
    float* Qs = sm;                 // BQ*SQ
    float* Ks = Qs + BQ * SQ;       // BKT*SKS
    float* Vs = Ks + BKT * SKS;     // BKT*SV
    float* Ps = Vs + BKT * SV;      // BQ*SP

    int h = blockIdx.y;
    int qt = gridDim.x - 1 - blockIdx.x;   // largest q-tile first
    int q0 = qt * BQ;
    int kvh = h >> 2;
    int tid = threadIdx.x;
    int tx = tid & 15;
    int ty = tid >> 4;

    // load Q tile: 64 rows x 128 cols
#pragma unroll
    for (int it = 0; it < 8; it++) {
        int idx = tid + it * 256;
        int r = idx >> 5;
        int c4 = (idx & 31) << 2;
        float4 v = *(const float4*)(Q + (size_t)(q0 + r) * QDIM + h * HD + c4);
        Qs[r * SQ + c4 + 0] = v.x;
        Qs[r * SQ + c4 + 1] = v.y;
        Qs[r * SQ + c4 + 2] = v.z;
        Qs[r * SQ + c4 + 3] = v.w;
    }

    float m_i[4], l_i[4], o_acc[4][8];
#pragma unroll
    for (int i = 0; i < 4; i++) {
        m_i[i] = -INFINITY;
        l_i[i] = 0.f;
#pragma unroll
        for (int j = 0; j < 8; j++) o_acc[i][j] = 0.f;
    }

    const float scale = 0.08838834764831845f;  // 1/sqrt(128)
    int ntiles = qt + 1;

    for (int t = 0; t < ntiles; t++) {
        int kb = t * BKT;
        __syncthreads();   // protect Ks/Vs/Ps from previous iteration (and Qs on t=0)
        // load K,V tiles
#pragma unroll
        for (int it = 0; it < 8; it++) {
            int idx = tid + it * 256;
            int r = idx >> 5;
            int c4 = (idx & 31) << 2;
            float4 kv = *(const float4*)(Kb + (size_t)(kb + r) * KVDIM + kvh * HD + c4);
            Ks[r * SKS + c4 + 0] = kv.x;
            Ks[r * SKS + c4 + 1] = kv.y;
            Ks[r * SKS + c4 + 2] = kv.z;
            Ks[r * SKS + c4 + 3] = kv.w;
            float4 vv = *(const float4*)(Vb + (size_t)(kb + r) * KVDIM + kvh * HD + c4);
            Vs[r * SV + c4 + 0] = vv.x;
            Vs[r * SV + c4 + 1] = vv.y;
            Vs[r * SV + c4 + 2] = vv.z;
            Vs[r * SV + c4 + 3] = vv.w;
        }
        __syncthreads();

        // ---- scores S = Q K^T ----
        float s[4][4];
#pragma unroll
        for (int i = 0; i < 4; i++)
#pragma unroll
            for (int j = 0; j < 4; j++) s[i][j] = 0.f;

        for (int d = 0; d < HD; d++) {
            float qf[4], kf[4];
#pragma unroll
            for (int i = 0; i < 4; i++) qf[i] = Qs[(ty * 4 + i) * SQ + d];
#pragma unroll
            for (int j = 0; j < 4; j++) kf[j] = Ks[(tx * 4 + j) * SKS + d];
#pragma unroll
            for (int i = 0; i < 4; i++)
#pragma unroll
                for (int j = 0; j < 4; j++)
                    s[i][j] += qf[i] * kf[j];
        }

        bool diag = (kb + BKT > q0);  // only the last (diagonal) tile needs masking
#pragma unroll
        for (int i = 0; i < 4; i++)
#pragma unroll
            for (int j = 0; j < 4; j++) {
                float v = s[i][j] * scale;
                if (diag && (kb + tx * 4 + j > q0 + ty * 4 + i)) v = -INFINITY;
                s[i][j] = v;
            }

        // ---- online softmax ----
#pragma unroll
        for (int i = 0; i < 4; i++) {
            float rmax = fmaxf(fmaxf(s[i][0], s[i][1]), fmaxf(s[i][2], s[i][3]));
#pragma unroll
            for (int off = 1; off < 16; off <<= 1)
                rmax = fmaxf(rmax, __shfl_xor_sync(0xffffffffu, rmax, off));
            float mn = fmaxf(m_i[i], rmax);
            float corr = __expf(m_i[i] - mn);
            m_i[i] = mn;
            float ps = 0.f;
#pragma unroll
            for (int j = 0; j < 4; j++) {
                float p = __expf(s[i][j] - mn);
                s[i][j] = p;
                ps += p;
            }
#pragma unroll
            for (int off = 1; off < 16; off <<= 1)
                ps += __shfl_xor_sync(0xffffffffu, ps, off);
            l_i[i] = l_i[i] * corr + ps;
#pragma unroll
            for (int j = 0; j < 8; j++) o_acc[i][j] *= corr;
        }

        // write P, then P @ V
#pragma unroll
        for (int i = 0; i < 4; i++)
#pragma unroll
            for (int j = 0; j < 4; j++)
                Ps[(ty * 4 + i) * SP + tx * 4 + j] = s[i][j];
        __syncthreads();

        for (int kk = 0; kk < BKT; kk++) {
            float pf[4];
#pragma unroll
            for (int i = 0; i < 4; i++) pf[i] = Ps[(ty * 4 + i) * SP + kk];
            float4 v0 = *(const float4*)&Vs[kk * SV + tx * 8];
            float4 v1 = *(const float4*)&Vs[kk * SV + tx * 8 + 4];
            float vf[8] = {v0.x, v0.y, v0.z, v0.w, v1.x, v1.y, v1.z, v1.w};
#pragma unroll
            for (int i = 0; i < 4; i++)
#pragma unroll
                for (int j = 0; j < 8; j++)
                    o_acc[i][j] += pf[i] * vf[j];
        }
    }

    // epilogue
#pragma unroll
    for (int i = 0; i < 4; i++) {
        float inv = 1.f / l_i[i];
        int r = q0 + ty * 4 + i;
        float4 w0 = make_float4(o_acc[i][0] * inv, o_acc[i][1] * inv,
                                o_acc[i][2] * inv, o_acc[i][3] * inv);
        float4 w1 = make_float4(o_acc[i][4] * inv, o_acc[i][5] * inv,
                                o_acc[i][6] * inv, o_acc[i][7] * inv);
        float* dst = O + (size_t)r * QDIM + h * HD + tx * 8;
        *(float4*)dst = w0;
        *(float4*)(dst + 4) = w1;
    }
}

// ======================================================================
// Launch
// ======================================================================
extern "C" void kernel_launch(void* const* d_in, const int* in_sizes, int n_in,
                              void* d_out, int out_size)
{
    const float* x        = (const float*)d_in[0];
    const float* cosb     = (const float*)d_in[1];
    const float* sinb     = (const float*)d_in[2];
    const float* q_scales = (const float*)d_in[3];
    const float* q_bias   = (const float*)d_in[4];
    const float* k_scales = (const float*)d_in[5];
    const float* k_bias   = (const float*)d_in[6];
    const float* v_scales = (const float*)d_in[7];
    const float* v_bias   = (const float*)d_in[8];
    const float* o_scales = (const float*)d_in[9];
    const int* q_qweight  = (const int*)d_in[10];
    const int* q_qzeros   = (const int*)d_in[11];
    const int* k_qweight  = (const int*)d_in[12];
    const int* k_qzeros   = (const int*)d_in[13];
    const int* v_qweight  = (const int*)d_in[14];
    const int* v_qzeros   = (const int*)d_in[15];
    const int* o_qweight  = (const int*)d_in[16];
    const int* o_qzeros   = (const int*)d_in[17];
    float* out = (float*)d_out;

    float *pq, *pk, *pv, *pa;
    cudaGetSymbolAddress((void**)&pq, g_q);
    cudaGetSymbolAddress((void**)&pk, g_k);
    cudaGetSymbolAddress((void**)&pv, g_v);
    cudaGetSymbolAddress((void**)&pa, g_a);

    // QKV projections
    {
        dim3 blk(256);
        dim3 gq(QDIM / BN, S_LEN / BM);
        gemm_q4_kernel<<<gq, blk>>>(x, q_qweight, q_scales, q_qzeros, q_bias,
                                    pq, S_LEN, QDIM, HIDDEN);
        dim3 gk(KVDIM / BN, S_LEN / BM);
        gemm_q4_kernel<<<gk, blk>>>(x, k_qweight, k_scales, k_qzeros, k_bias,
                                    pk, S_LEN, KVDIM, HIDDEN);
        gemm_q4_kernel<<<gk, blk>>>(x, v_qweight, v_scales, v_qzeros, v_bias,
                                    pv, S_LEN, KVDIM, HIDDEN);
    }

    // RoPE in-place on Q and K
    {
        dim3 grid(NH + NKV, S_LEN);
        rope_kernel<<<grid, 64>>>(pq, pk, cosb, sinb);
    }

    // Flash attention
    {
        size_t smem = (size_t)(BQ * SQ + BKT * SKS + BKT * SV + BQ * SP) * sizeof(float);
        cudaFuncSetAttribute(flash_kernel,
                             cudaFuncAttributeMaxDynamicSharedMemorySize, (int)smem);
        dim3 grid(S_LEN / BQ, NH);
        flash_kernel<<<grid, 256, smem>>>(pq, pk, pv, pa);
    }

    // Output projection (no bias)
    {
        dim3 blk(256);
        dim3 go(HIDDEN / BN, S_LEN / BM);
        gemm_q4_kernel<<<go, blk>>>(pa, o_qweight, o_scales, o_qzeros, nullptr,
                                    out, S_LEN, HIDDEN, QDIM);
    }
}

// round 3
// speedup vs baseline: 1.6977x; 1.6977x over previous
#include <cuda_runtime.h>
#include <cuda_bf16.h>
#include <math.h>

// Problem constants
#define S_LEN 2048
#define HIDDEN 2560
#define NH 32
#define NKV 8
#define HD 128
#define QDIM (NH*HD)    // 4096
#define KVDIM (NKV*HD)  // 1024
#define GS 128

// -------- scratch (static device arrays; no allocation allowed) --------
__device__ float g_q[S_LEN * QDIM];   // 33.5 MB
__device__ float g_k[S_LEN * KVDIM];  // 8.4 MB
__device__ float g_v[S_LEN * KVDIM];  // 8.4 MB
__device__ float g_a[S_LEN * QDIM];   // 33.5 MB

// ======================================================================
// bf16x3 error-compensated tensor-core dequant GEMM
//   C[M,N] = A[M,K] @ W[K,N] (+bias),   W from AWQ int4
// Each operand split x = hi + lo (bf16 each); product = hi*hi + hi*lo + lo*hi
// residual ~2^-16 -> dot-product rel err ~1.5e-5.
// BM=128 BN=128 BK=32. 256 threads = 8 warps (2x4), warp tile 64x32.
// mma.sync.aligned.m16n8k16.row.col.f32.bf16.bf16.f32
// ======================================================================
#define BM 128
#define BN 128
#define BK 32
#define KPW (BK/2)    // 16 u32 k-pair words per row
#define AST 20        // padded stride (words): g*20+t distinct banks
#define BST 20

__device__ __forceinline__ void split2(float f0, float f1,
                                       unsigned &hi, unsigned &lo) {
    __nv_bfloat16 h0 = __float2bfloat16(f0);
    __nv_bfloat16 h1 = __float2bfloat16(f1);
    __nv_bfloat16 l0 = __float2bfloat16(f0 - __bfloat162float(h0));
    __nv_bfloat16 l1 = __float2bfloat16(f1 - __bfloat162float(h1));
    hi = (unsigned)__bfloat16_as_ushort(h0) |
         ((unsigned)__bfloat16_as_ushort(h1) << 16);
    lo = (unsigned)__bfloat16_as_ushort(l0) |
         ((unsigned)__bfloat16_as_ushort(l1) << 16);
}

__device__ __forceinline__ void mma_bf16(float c[4],
                                         unsigned a0, unsigned a1, unsigned a2, unsigned a3,
                                         unsigned b0, unsigned b1) {
    asm volatile(
        "mma.sync.aligned.m16n8k16.row.col.f32.bf16.bf16.f32 "
        "{%0,%1,%2,%3}, {%4,%5,%6,%7}, {%8,%9}, {%0,%1,%2,%3};"
        : "+f"(c[0]), "+f"(c[1]), "+f"(c[2]), "+f"(c[3])
        : "r"(a0), "r"(a1), "r"(a2), "r"(a3), "r"(b0), "r"(b1));
}

__global__ __launch_bounds__(256)
void gemm_q4_tc_kernel(const float* __restrict__ A,
                       const int*   __restrict__ qw,
                       const float* __restrict__ sc,
                       const int*   __restrict__ qz,
                       const float* __restrict__ bias,
                       float* __restrict__ C,
                       int M, int N, int K)
{
    __shared__ unsigned AsH[BM][AST], AsL[BM][AST];   // [m][kpair]
    __shared__ unsigned BsH[BN][BST], BsL[BN][BST];   // [n][kpair]

    int tid  = threadIdx.x;
    int lane = tid & 31;
    int warp = tid >> 5;
    int warp_m = warp & 1;        // 0..1 -> 64-row slabs
    int warp_n = warp >> 1;       // 0..3 -> 32-col slabs
    int bm = blockIdx.y * BM;
    int bn = blockIdx.x * BN;
    int t = lane & 3;             // thread-in-group
    int g = lane >> 2;            // group id

    // ---- A global-load mapping: 1024 float4, 4 per thread ----
    int arow[4], akp[4];
#pragma unroll
    for (int i = 0; i < 4; i++) {
        int idx = tid + i * 256;
        arow[i] = idx >> 3;
        akp[i]  = (idx & 7) << 1;   // k-pair index (float4 = 2 pairs)
    }
    // ---- B mapping: 128 n-cols x 4 packed k-words, 2 words/thread ----
    int n_loc = tid & 127;
    int kp0   = (tid >> 7) << 1;    // packed-word index within tile: 0 or 2

    float acc[4][4][4];
#pragma unroll
    for (int mi = 0; mi < 4; mi++)
#pragma unroll
        for (int ni = 0; ni < 4; ni++)
#pragma unroll
            for (int r = 0; r < 4; r++) acc[mi][ni][r] = 0.f;

    // ---- stage registers (prefetch) ----
    float4 aR[4];
    unsigned bw[2];
    float bz, bs_;

#pragma unroll
    for (int i = 0; i < 4; i++)
        aR[i] = *(const float4*)(A + (size_t)(bm + arow[i]) * K + (akp[i] << 1));
    {
        const int* qwp = qw + (size_t)kp0 * N + bn + n_loc;
        bw[0] = (unsigned)qwp[0];
        bw[1] = (unsigned)qwp[N];
        bz = (float)qz[bn + n_loc];
        bs_ = sc[bn + n_loc];
    }

    for (int k0 = 0; k0 < K; k0 += BK) {
        // ---- commit staged tile to smem (split hi/lo) ----
#pragma unroll
        for (int i = 0; i < 4; i++) {
            unsigned h, l;
            split2(aR[i].x, aR[i].y, h, l);
            AsH[arow[i]][akp[i]]     = h;  AsL[arow[i]][akp[i]]     = l;
            split2(aR[i].z, aR[i].w, h, l);
            AsH[arow[i]][akp[i] + 1] = h;  AsL[arow[i]][akp[i] + 1] = l;
        }
#pragma unroll
        for (int i = 0; i < 2; i++) {
            unsigned q = bw[i];
            int kpb = (kp0 + i) * 4;     // 4 k-pairs per packed word
#pragma unroll
            for (int j = 0; j < 4; j++) {
                float f0 = ((float)((q >> (8 * j))     & 15u) - bz) * bs_;
                float f1 = ((float)((q >> (8 * j + 4)) & 15u) - bz) * bs_;
                unsigned h, l;
                split2(f0, f1, h, l);
                BsH[n_loc][kpb + j] = h;
                BsL[n_loc][kpb + j] = l;
            }
        }
        __syncthreads();

        // ---- prefetch next tile (overlaps MMA) ----
        int kn = k0 + BK;
        if (kn < K) {
#pragma unroll
            for (int i = 0; i < 4; i++)
                aR[i] = *(const float4*)(A + (size_t)(bm + arow[i]) * K + kn + (akp[i] << 1));
            const int* qwp = qw + (size_t)((kn >> 3) + kp0) * N + bn + n_loc;
            bw[0] = (unsigned)qwp[0];
            bw[1] = (unsigned)qwp[N];
            int grp = kn >> 7;
            bz = (float)qz[(size_t)grp * N + bn + n_loc];
            bs_ = sc[(size_t)grp * N + bn + n_loc];
        }

        // ---- MMA: 2 k16 steps ----
#pragma unroll
        for (int ks = 0; ks < 2; ks++) {
            int kpb = ks * 8;
            unsigned ah[4][4], al[4][4];
#pragma unroll
            for (int mi = 0; mi < 4; mi++) {
                int r = warp_m * 64 + mi * 16 + g;
                ah[mi][0] = AsH[r][kpb + t];
                ah[mi][1] = AsH[r + 8][kpb + t];
                ah[mi][2] = AsH[r][kpb + t + 4];
                ah[mi][3] = AsH[r + 8][kpb + t + 4];
                al[mi][0] = AsL[r][kpb + t];
                al[mi][1] = AsL[r + 8][kpb + t];
                al[mi][2] = AsL[r][kpb + t + 4];
                al[mi][3] = AsL[r + 8][kpb + t + 4];
            }
            unsigned bh[4][2], bl[4][2];
#pragma unroll
            for (int ni = 0; ni < 4; ni++) {
                int c = warp_n * 32 + ni * 8 + g;
                bh[ni][0] = BsH[c][kpb + t];
                bh[ni][1] = BsH[c][kpb + t + 4];
                bl[ni][0] = BsL[c][kpb + t];
                bl[ni][1] = BsL[c][kpb + t + 4];
            }
#pragma unroll
            for (int mi = 0; mi < 4; mi++)
#pragma unroll
                for (int ni = 0; ni < 4; ni++) {
                    mma_bf16(acc[mi][ni], ah[mi][0], ah[mi][1], ah[mi][2], ah[mi][3],
                             bh[ni][0], bh[ni][1]);
                    mma_bf16(acc[mi][ni], ah[mi][0], ah[mi][1], ah[mi][2], ah[mi][3],
                             bl[ni][0], bl[ni][1]);
                    mma_bf16(acc[mi][ni], al[mi][0], al[mi][1], al[mi][2], al[mi][3],
                             bh[ni][0], bh[ni][1]);
                }
        }
        __syncthreads();
    }

    // ---- epilogue: c-frag rows g (+8), cols 2t (+1) ----
#pragma unroll
    for (int ni = 0; ni < 4; ni++) {
        int n = bn + warp_n * 32 + ni * 8 + (t << 1);
        float b0 = 0.f, b1 = 0.f;
        if (bias) { b0 = bias[n]; b1 = bias[n + 1]; }
#pragma unroll
        for (int mi = 0; mi < 4; mi++) {
            int m = bm + warp_m * 64 + mi * 16 + g;
            float2 v0 = make_float2(acc[mi][ni][0] + b0, acc[mi][ni][1] + b1);
            float2 v1 = make_float2(acc[mi][ni][2] + b0, acc[mi][ni][3] + b1);
            *(float2*)(C + (size_t)m * N + n) = v0;
            *(float2*)(C + (size_t)(m + 8) * N + n) = v1;
        }
    }
}

// ======================================================================
// RoPE (in-place). blockIdx.x: head 0..39 (0..31 Q, 32..39 K), blockIdx.y: s
// ======================================================================
__global__ void rope_kernel(float* __restrict__ Qb, float* __restrict__ Kb,
                            const float* __restrict__ cosb,
                            const float* __restrict__ sinb)
{
    int s = blockIdx.y;
    int h = blockIdx.x;
    int d = threadIdx.x;  // 0..63
    float c1 = cosb[s * HD + d];
    float s1 = sinb[s * HD + d];
    float c2 = cosb[s * HD + d + 64];
    float s2 = sinb[s * HD + d + 64];
    float* base = (h < NH) ? (Qb + (size_t)s * QDIM + h * HD)
                           : (Kb + (size_t)s * KVDIM + (h - NH) * HD);
    float x1 = base[d];
    float x2 = base[d + 64];
    base[d]      = x1 * c1 - x2 * s1;
    base[d + 64] = x2 * c2 + x1 * s2;
}

// ======================================================================
// Flash attention, fp32, causal, GQA (4 Q-heads per KV head)
// BQ=64, BKT=64. 256 threads: tx 0..15 (k / dcols), ty 0..15 (q rows)
// ======================================================================
#define BQ 64
#define BKT 64
#define SQ 132
#define SKS 129
#define SV 132
#define SP 65

__global__ __launch_bounds__(256)
void flash_kernel(const float* __restrict__ Q,
                  const float* __restrict__ Kb,
                  const float* __restrict__ Vb,
                  float* __restrict__ O)
{
    extern __shared__ float sm[];
    float* Qs = sm;
    float* Ks = Qs + BQ * SQ;
    float* Vs = Ks + BKT * SKS;
    float* Ps = Vs + BKT * SV;

    int h = blockIdx.y;
    int qt = gridDim.x - 1 - blockIdx.x;
    int q0 = qt * BQ;
    int kvh = h >> 2;
    int tid = threadIdx.x;
    int tx = tid & 15;
    int ty = tid >> 4;

#pragma unroll
    for (int it = 0; it < 8; it++) {
        int idx = tid + it * 256;
        int r = idx >> 5;
        int c4 = (idx & 31) << 2;
        float4 v = *(const float4*)(Q + (size_t)(q0 + r) * QDIM + h * HD + c4);
        Qs[r * SQ + c4 + 0] = v.x;
        Qs[r * SQ + c4 + 1] = v.y;
        Qs[r * SQ + c4 + 2] = v.z;
        Qs[r * SQ + c4 + 3] = v.w;
    }

    float m_i[4], l_i[4], o_acc[4][8];
#pragma unroll
    for (int i = 0; i < 4; i++) {
        m_i[i] = -INFINITY;
        l_i[i] = 0.f;
#pragma unroll
        for (int j = 0; j < 8; j++) o_acc[i][j] = 0.f;
    }

    const float scale = 0.08838834764831845f;
    int ntiles = qt + 1;

    for (int tt = 0; tt < ntiles; tt++) {
        int kb = tt * BKT;
        __syncthreads();
#pragma unroll
        for (int it = 0; it < 8; it++) {
            int idx = tid + it * 256;
            int r = idx >> 5;
            int c4 = (idx & 31) << 2;
            float4 kv = *(const float4*)(Kb + (size_t)(kb + r) * KVDIM + kvh * HD + c4);
            Ks[r * SKS + c4 + 0] = kv.x;
            Ks[r * SKS + c4 + 1] = kv.y;
            Ks[r * SKS + c4 + 2] = kv.z;
            Ks[r * SKS + c4 + 3] = kv.w;
            float4 vv = *(const float4*)(Vb + (size_t)(kb + r) * KVDIM + kvh * HD + c4);
            Vs[r * SV + c4 + 0] = vv.x;
            Vs[r * SV + c4 + 1] = vv.y;
            Vs[r * SV + c4 + 2] = vv.z;
            Vs[r * SV + c4 + 3] = vv.w;
        }
        __syncthreads();

        float s[4][4];
#pragma unroll
        for (int i = 0; i < 4; i++)
#pragma unroll
            for (int j = 0; j < 4; j++) s[i][j] = 0.f;

        for (int d = 0; d < HD; d++) {
            float qf[4], kf[4];
#pragma unroll
            for (int i = 0; i < 4; i++) qf[i] = Qs[(ty * 4 + i) * SQ + d];
#pragma unroll
            for (int j = 0; j < 4; j++) kf[j] = Ks[(tx * 4 + j) * SKS + d];
#pragma unroll
            for (int i = 0; i < 4; i++)
#pragma unroll
                for (int j = 0; j < 4; j++)
                    s[i][j] += qf[i] * kf[j];
        }

        bool diag = (kb + BKT > q0);
#pragma unroll
        for (int i = 0; i < 4; i++)
#pragma unroll
            for (int j = 0; j < 4; j++) {
                float v = s[i][j] * scale;
                if (diag && (kb + tx * 4 + j > q0 + ty * 4 + i)) v = -INFINITY;
                s[i][j] = v;
            }

#pragma unroll
        for (int i = 0; i < 4; i++) {
            float rmax = fmaxf(fmaxf(s[i][0], s[i][1]), fmaxf(s[i][2], s[i][3]));
#pragma unroll
            for (int off = 1; off < 16; off <<= 1)
                rmax = fmaxf(rmax, __shfl_xor_sync(0xffffffffu, rmax, off));
            float mn = fmaxf(m_i[i], rmax);
            float corr = __expf(m_i[i] - mn);
            m_i[i] = mn;
            float ps = 0.f;
#pragma unroll
            for (int j = 0; j < 4; j++) {
                float p = __expf(s[i][j] - mn);
                s[i][j] = p;
                ps += p;
            }
#pragma unroll
            for (int off = 1; off < 16; off <<= 1)
                ps += __shfl_xor_sync(0xffffffffu, ps, off);
            l_i[i] = l_i[i] * corr + ps;
#pragma unroll
            for (int j = 0; j < 8; j++) o_acc[i][j] *= corr;
        }

#pragma unroll
        for (int i = 0; i < 4; i++)
#pragma unroll
            for (int j = 0; j < 4; j++)
                Ps[(ty * 4 + i) * SP + tx * 4 + j] = s[i][j];
        __syncthreads();

        for (int kk = 0; kk < BKT; kk++) {
            float pf[4];
#pragma unroll
            for (int i = 0; i < 4; i++) pf[i] = Ps[(ty * 4 + i) * SP + kk];
            float4 v0 = *(const float4*)&Vs[kk * SV + tx * 8];
            float4 v1 = *(const float4*)&Vs[kk * SV + tx * 8 + 4];
            float vf[8] = {v0.x, v0.y, v0.z, v0.w, v1.x, v1.y, v1.z, v1.w};
#pragma unroll
            for (int i = 0; i < 4; i++)
#pragma unroll
                for (int j = 0; j < 8; j++)
                    o_acc[i][j] += pf[i] * vf[j];
        }
    }

#pragma unroll
    for (int i = 0; i < 4; i++) {
        float inv = 1.f / l_i[i];
        int r = q0 + ty * 4 + i;
        float4 w0 = make_float4(o_acc[i][0] * inv, o_acc[i][1] * inv,
                                o_acc[i][2] * inv, o_acc[i][3] * inv);
        float4 w1 = make_float4(o_acc[i][4] * inv, o_acc[i][5] * inv,
                                o_acc[i][6] * inv, o_acc[i][7] * inv);
        float* dst = O + (size_t)r * QDIM + h * HD + tx * 8;
        *(float4*)dst = w0;
        *(float4*)(dst + 4) = w1;
    }
}

// ======================================================================
// Launch
// ======================================================================
extern "C" void kernel_launch(void* const* d_in, const int* in_sizes, int n_in,
                              void* d_out, int out_size)
{
    const float* x        = (const float*)d_in[0];
    const float* cosb     = (const float*)d_in[1];
    const float* sinb     = (const float*)d_in[2];
    const float* q_scales = (const float*)d_in[3];
    const float* q_bias   = (const float*)d_in[4];
    const float* k_scales = (const float*)d_in[5];
    const float* k_bias   = (const float*)d_in[6];
    const float* v_scales = (const float*)d_in[7];
    const float* v_bias   = (const float*)d_in[8];
    const float* o_scales = (const float*)d_in[9];
    const int* q_qweight  = (const int*)d_in[10];
    const int* q_qzeros   = (const int*)d_in[11];
    const int* k_qweight  = (const int*)d_in[12];
    const int* k_qzeros   = (const int*)d_in[13];
    const int* v_qweight  = (const int*)d_in[14];
    const int* v_qzeros   = (const int*)d_in[15];
    const int* o_qweight  = (const int*)d_in[16];
    const int* o_qzeros   = (const int*)d_in[17];
    float* out = (float*)d_out;

    float *pq, *pk, *pv, *pa;
    cudaGetSymbolAddress((void**)&pq, g_q);
    cudaGetSymbolAddress((void**)&pk, g_k);
    cudaGetSymbolAddress((void**)&pv, g_v);
    cudaGetSymbolAddress((void**)&pa, g_a);

    // QKV projections (bf16x3 tensor cores)
    {
        dim3 blk(256);
        dim3 gq(QDIM / BN, S_LEN / BM);
        gemm_q4_tc_kernel<<<gq, blk>>>(x, q_qweight, q_scales, q_qzeros, q_bias,
                                       pq, S_LEN, QDIM, HIDDEN);
        dim3 gk(KVDIM / BN, S_LEN / BM);
        gemm_q4_tc_kernel<<<gk, blk>>>(x, k_qweight, k_scales, k_qzeros, k_bias,
                                       pk, S_LEN, KVDIM, HIDDEN);
        gemm_q4_tc_kernel<<<gk, blk>>>(x, v_qweight, v_scales, v_qzeros, v_bias,
                                       pv, S_LEN, KVDIM, HIDDEN);
    }

    // RoPE in-place on Q and K
    {
        dim3 grid(NH + NKV, S_LEN);
        rope_kernel<<<grid, 64>>>(pq, pk, cosb, sinb);
    }

    // Flash attention
    {
        size_t smem = (size_t)(BQ * SQ + BKT * SKS + BKT * SV + BQ * SP) * sizeof(float);
        cudaFuncSetAttribute(flash_kernel,
                             cudaFuncAttributeMaxDynamicSharedMemorySize, (int)smem);
        dim3 grid(S_LEN / BQ, NH);
        flash_kernel<<<grid, 256, smem>>>(pq, pk, pv, pa);
    }

    // Output projection (no bias)
    {
        dim3 blk(256);
        dim3 go(HIDDEN / BN, S_LEN / BM);
        gemm_q4_tc_kernel<<<go, blk>>>(pa, o_qweight, o_scales, o_qzeros, nullptr,
                                       out, S_LEN, HIDDEN, QDIM);
    }
}

// round 4
// speedup vs baseline: 2.4463x; 1.4409x over previous
#include <cuda_runtime.h>
#include <cuda_bf16.h>
#include <math.h>

// Problem constants
#define S_LEN 2048
#define HIDDEN 2560
#define NH 32
#define NKV 8
#define HD 128
#define QDIM (NH*HD)    // 4096
#define KVDIM (NKV*HD)  // 1024
#define GS 128

// -------- scratch (static device arrays; no allocation allowed) --------
__device__ float g_q[S_LEN * QDIM];   // 33.5 MB
__device__ float g_k[S_LEN * KVDIM];  // 8.4 MB
__device__ float g_v[S_LEN * KVDIM];  // 8.4 MB
__device__ float g_a[S_LEN * QDIM];   // 33.5 MB

// ======================================================================
// shared helpers
// ======================================================================
__device__ __forceinline__ void split2(float f0, float f1,
                                       unsigned &hi, unsigned &lo) {
    __nv_bfloat16 h0 = __float2bfloat16(f0);
    __nv_bfloat16 h1 = __float2bfloat16(f1);
    __nv_bfloat16 l0 = __float2bfloat16(f0 - __bfloat162float(h0));
    __nv_bfloat16 l1 = __float2bfloat16(f1 - __bfloat162float(h1));
    hi = (unsigned)__bfloat16_as_ushort(h0) |
         ((unsigned)__bfloat16_as_ushort(h1) << 16);
    lo = (unsigned)__bfloat16_as_ushort(l0) |
         ((unsigned)__bfloat16_as_ushort(l1) << 16);
}

__device__ __forceinline__ void mma_bf16(float c[4],
                                         unsigned a0, unsigned a1, unsigned a2, unsigned a3,
                                         unsigned b0, unsigned b1) {
    asm volatile(
        "mma.sync.aligned.m16n8k16.row.col.f32.bf16.bf16.f32 "
        "{%0,%1,%2,%3}, {%4,%5,%6,%7}, {%8,%9}, {%0,%1,%2,%3};"
        : "+f"(c[0]), "+f"(c[1]), "+f"(c[2]), "+f"(c[3])
        : "r"(a0), "r"(a1), "r"(a2), "r"(a3), "r"(b0), "r"(b1));
}

__device__ __forceinline__ void ldsm_x2_trans(unsigned &r0, unsigned &r1, unsigned addr) {
    asm volatile("ldmatrix.sync.aligned.m8n8.x2.trans.shared.b16 {%0,%1}, [%2];"
                 : "=r"(r0), "=r"(r1) : "r"(addr));
}

__device__ __forceinline__ unsigned smem_u32(const void* p) {
    return (unsigned)__cvta_generic_to_shared(p);
}

// ======================================================================
// bf16x3 dequant GEMM (unchanged from R3; validated)
// ======================================================================
#define BM 128
#define BN 128
#define BK 32
#define AST 20
#define BST 20

__global__ __launch_bounds__(256)
void gemm_q4_tc_kernel(const float* __restrict__ A,
                       const int*   __restrict__ qw,
                       const float* __restrict__ sc,
                       const int*   __restrict__ qz,
                       const float* __restrict__ bias,
                       float* __restrict__ C,
                       int M, int N, int K)
{
    __shared__ unsigned AsH[BM][AST], AsL[BM][AST];
    __shared__ unsigned BsH[BN][BST], BsL[BN][BST];

    int tid  = threadIdx.x;
    int lane = tid & 31;
    int warp = tid >> 5;
    int warp_m = warp & 1;
    int warp_n = warp >> 1;
    int bm = blockIdx.y * BM;
    int bn = blockIdx.x * BN;
    int t = lane & 3;
    int g = lane >> 2;

    int arow[4], akp[4];
#pragma unroll
    for (int i = 0; i < 4; i++) {
        int idx = tid + i * 256;
        arow[i] = idx >> 3;
        akp[i]  = (idx & 7) << 1;
    }
    int n_loc = tid & 127;
    int kp0   = (tid >> 7) << 1;

    float acc[4][4][4];
#pragma unroll
    for (int mi = 0; mi < 4; mi++)
#pragma unroll
        for (int ni = 0; ni < 4; ni++)
#pragma unroll
            for (int r = 0; r < 4; r++) acc[mi][ni][r] = 0.f;

    float4 aR[4];
    unsigned bw[2];
    float bz, bs_;

#pragma unroll
    for (int i = 0; i < 4; i++)
        aR[i] = *(const float4*)(A + (size_t)(bm + arow[i]) * K + (akp[i] << 1));
    {
        const int* qwp = qw + (size_t)kp0 * N + bn + n_loc;
        bw[0] = (unsigned)qwp[0];
        bw[1] = (unsigned)qwp[N];
        bz = (float)qz[bn + n_loc];
        bs_ = sc[bn + n_loc];
    }

    for (int k0 = 0; k0 < K; k0 += BK) {
#pragma unroll
        for (int i = 0; i < 4; i++) {
            unsigned h, l;
            split2(aR[i].x, aR[i].y, h, l);
            AsH[arow[i]][akp[i]]     = h;  AsL[arow[i]][akp[i]]     = l;
            split2(aR[i].z, aR[i].w, h, l);
            AsH[arow[i]][akp[i] + 1] = h;  AsL[arow[i]][akp[i] + 1] = l;
        }
#pragma unroll
        for (int i = 0; i < 2; i++) {
            unsigned q = bw[i];
            int kpb = (kp0 + i) * 4;
#pragma unroll
            for (int j = 0; j < 4; j++) {
                float f0 = ((float)((q >> (8 * j))     & 15u) - bz) * bs_;
                float f1 = ((float)((q >> (8 * j + 4)) & 15u) - bz) * bs_;
                unsigned h, l;
                split2(f0, f1, h, l);
                BsH[n_loc][kpb + j] = h;
                BsL[n_loc][kpb + j] = l;
            }
        }
        __syncthreads();

        int kn = k0 + BK;
        if (kn < K) {
#pragma unroll
            for (int i = 0; i < 4; i++)
                aR[i] = *(const float4*)(A + (size_t)(bm + arow[i]) * K + kn + (akp[i] << 1));
            const int* qwp = qw + (size_t)((kn >> 3) + kp0) * N + bn + n_loc;
            bw[0] = (unsigned)qwp[0];
            bw[1] = (unsigned)qwp[N];
            int grp = kn >> 7;
            bz = (float)qz[(size_t)grp * N + bn + n_loc];
            bs_ = sc[(size_t)grp * N + bn + n_loc];
        }

#pragma unroll
        for (int ks = 0; ks < 2; ks++) {
            int kpb = ks * 8;
            unsigned ah[4][4], al[4][4];
#pragma unroll
            for (int mi = 0; mi < 4; mi++) {
                int r = warp_m * 64 + mi * 16 + g;
                ah[mi][0] = AsH[r][kpb + t];
                ah[mi][1] = AsH[r + 8][kpb + t];
                ah[mi][2] = AsH[r][kpb + t + 4];
                ah[mi][3] = AsH[r + 8][kpb + t + 4];
                al[mi][0] = AsL[r][kpb + t];
                al[mi][1] = AsL[r + 8][kpb + t];
                al[mi][2] = AsL[r][kpb + t + 4];
                al[mi][3] = AsL[r + 8][kpb + t + 4];
            }
            unsigned bh[4][2], bl[4][2];
#pragma unroll
            for (int ni = 0; ni < 4; ni++) {
                int c = warp_n * 32 + ni * 8 + g;
                bh[ni][0] = BsH[c][kpb + t];
                bh[ni][1] = BsH[c][kpb + t + 4];
                bl[ni][0] = BsL[c][kpb + t];
                bl[ni][1] = BsL[c][kpb + t + 4];
            }
#pragma unroll
            for (int mi = 0; mi < 4; mi++)
#pragma unroll
                for (int ni = 0; ni < 4; ni++) {
                    mma_bf16(acc[mi][ni], ah[mi][0], ah[mi][1], ah[mi][2], ah[mi][3],
                             bh[ni][0], bh[ni][1]);
                    mma_bf16(acc[mi][ni], ah[mi][0], ah[mi][1], ah[mi][2], ah[mi][3],
                             bl[ni][0], bl[ni][1]);
                    mma_bf16(acc[mi][ni], al[mi][0], al[mi][1], al[mi][2], al[mi][3],
                             bh[ni][0], bh[ni][1]);
                }
        }
        __syncthreads();
    }

#pragma unroll
    for (int ni = 0; ni < 4; ni++) {
        int n = bn + warp_n * 32 + ni * 8 + (t << 1);
        float b0 = 0.f, b1 = 0.f;
        if (bias) { b0 = bias[n]; b1 = bias[n + 1]; }
#pragma unroll
        for (int mi = 0; mi < 4; mi++) {
            int m = bm + warp_m * 64 + mi * 16 + g;
            float2 v0 = make_float2(acc[mi][ni][0] + b0, acc[mi][ni][1] + b1);
            float2 v1 = make_float2(acc[mi][ni][2] + b0, acc[mi][ni][3] + b1);
            *(float2*)(C + (size_t)m * N + n) = v0;
            *(float2*)(C + (size_t)(m + 8) * N + n) = v1;
        }
    }
}

// ======================================================================
// RoPE (unchanged)
// ======================================================================
__global__ void rope_kernel(float* __restrict__ Qb, float* __restrict__ Kb,
                            const float* __restrict__ cosb,
                            const float* __restrict__ sinb)
{
    int s = blockIdx.y;
    int h = blockIdx.x;
    int d = threadIdx.x;
    float c1 = cosb[s * HD + d];
    float s1 = sinb[s * HD + d];
    float c2 = cosb[s * HD + d + 64];
    float s2 = sinb[s * HD + d + 64];
    float* base = (h < NH) ? (Qb + (size_t)s * QDIM + h * HD)
                           : (Kb + (size_t)s * KVDIM + (h - NH) * HD);
    float x1 = base[d];
    float x2 = base[d + 64];
    base[d]      = x1 * c1 - x2 * s1;
    base[d + 64] = x2 * c2 + x1 * s2;
}

// ======================================================================
// bf16x3 tensor-core flash attention
// BQ=128 (8 warps x 16 rows), BKT=64, HD=128, causal, GQA
// K/V smem: [token][d-pair] words, stride 68 (hi+lo planes). 68 KB total.
// Scores: A=Q (regs, hi/lo), B=K via direct LDS (conflict-free).
// PV:     A=P (from score C-frags, regs), B=V via ldmatrix.x2.trans.
// ======================================================================
#define FBQ 128
#define FBK 64
#define KVW 68               // words per smem row (64 data + 4 pad)
#define FPLANE (FBK * KVW)   // 4352 words per plane

__global__ __launch_bounds__(256, 1)
void flash_tc_kernel(const float* __restrict__ Q,
                     const float* __restrict__ Kb,
                     const float* __restrict__ Vb,
                     float* __restrict__ O)
{
    extern __shared__ unsigned fsm[];
    unsigned (*KsH)[KVW] = (unsigned(*)[KVW])(fsm);
    unsigned (*KsL)[KVW] = (unsigned(*)[KVW])(fsm + FPLANE);
    unsigned (*VsH)[KVW] = (unsigned(*)[KVW])(fsm + 2 * FPLANE);
    unsigned (*VsL)[KVW] = (unsigned(*)[KVW])(fsm + 3 * FPLANE);

    int h = blockIdx.y;
    int qt = gridDim.x - 1 - blockIdx.x;   // largest q-tile first
    int q0 = qt * FBQ;
    int kvh = h >> 2;
    int tid = threadIdx.x, lane = tid & 31, warp = tid >> 5;
    int t = lane & 3, g = lane >> 2;

    // ---- Q fragments, scale folded, split hi/lo (held in regs) ----
    unsigned qh[8][4], ql[8][4];
    {
        const float sc = 0.08838834764831845f;  // 1/sqrt(128)
        int r0 = q0 + warp * 16 + g;
        const float* p0 = Q + (size_t)r0 * QDIM + h * HD;
        const float* p1 = p0 + 8 * QDIM;
#pragma unroll
        for (int ks = 0; ks < 8; ks++) {
            int d = ks * 16 + 2 * t;
            float2 a0 = *(const float2*)(p0 + d);
            float2 a1 = *(const float2*)(p1 + d);
            float2 a2 = *(const float2*)(p0 + d + 8);
            float2 a3 = *(const float2*)(p1 + d + 8);
            split2(a0.x * sc, a0.y * sc, qh[ks][0], ql[ks][0]);
            split2(a1.x * sc, a1.y * sc, qh[ks][1], ql[ks][1]);
            split2(a2.x * sc, a2.y * sc, qh[ks][2], ql[ks][2]);
            split2(a3.x * sc, a3.y * sc, qh[ks][3], ql[ks][3]);
        }
    }

    float m0 = -INFINITY, m1 = -INFINITY, l0s = 0.f, l1s = 0.f;
    float o_acc[16][4];
#pragma unroll
    for (int nj = 0; nj < 16; nj++)
#pragma unroll
        for (int r = 0; r < 4; r++) o_acc[nj][r] = 0.f;

    unsigned vbH = smem_u32(VsH);
    unsigned vbL = smem_u32(VsL);

    int ntiles = (q0 + FBQ) >> 6;
    for (int tt = 0; tt < ntiles; tt++) {
        int kb = tt << 6;
        __syncthreads();
        // ---- load + split K,V tiles (coalesced; warp = one token row) ----
#pragma unroll
        for (int it = 0; it < 8; it++) {
            int idx = tid + it * 256;
            int r = idx >> 5;          // token 0..63
            int c = idx & 31;          // float4 index over d
            const float* kp = Kb + (size_t)(kb + r) * KVDIM + kvh * HD + c * 4;
            float4 kv = *(const float4*)kp;
            unsigned w0, w1, w2, w3;
            split2(kv.x, kv.y, w0, w1);
            split2(kv.z, kv.w, w2, w3);
            *(uint2*)&KsH[r][c * 2] = make_uint2(w0, w2);
            *(uint2*)&KsL[r][c * 2] = make_uint2(w1, w3);
            const float* vp = Vb + (size_t)(kb + r) * KVDIM + kvh * HD + c * 4;
            float4 vv = *(const float4*)vp;
            split2(vv.x, vv.y, w0, w1);
            split2(vv.z, vv.w, w2, w3);
            *(uint2*)&VsH[r][c * 2] = make_uint2(w0, w2);
            *(uint2*)&VsL[r][c * 2] = make_uint2(w1, w3);
        }
        __syncthreads();

        // ---- scores S = Q K^T (bf16x3) ----
        float s[8][4];
#pragma unroll
        for (int ni = 0; ni < 8; ni++)
#pragma unroll
            for (int r = 0; r < 4; r++) s[ni][r] = 0.f;

#pragma unroll
        for (int ks = 0; ks < 8; ks++) {
            int w = ks * 8 + t;
#pragma unroll
            for (int ni = 0; ni < 8; ni++) {
                int col = ni * 8 + g;
                unsigned bh0 = KsH[col][w], bh1 = KsH[col][w + 4];
                unsigned bl0 = KsL[col][w], bl1 = KsL[col][w + 4];
                mma_bf16(s[ni], qh[ks][0], qh[ks][1], qh[ks][2], qh[ks][3], bh0, bh1);
                mma_bf16(s[ni], qh[ks][0], qh[ks][1], qh[ks][2], qh[ks][3], bl0, bl1);
                mma_bf16(s[ni], ql[ks][0], ql[ks][1], ql[ks][2], ql[ks][3], bh0, bh1);
            }
        }

        // ---- causal mask (only last two tiles) ----
        if (kb + FBK > q0) {
            int r0 = q0 + warp * 16 + g, r1 = r0 + 8;
#pragma unroll
            for (int ni = 0; ni < 8; ni++) {
                int c0 = kb + ni * 8 + 2 * t, c1 = c0 + 1;
                if (c0 > r0) s[ni][0] = -INFINITY;
                if (c1 > r0) s[ni][1] = -INFINITY;
                if (c0 > r1) s[ni][2] = -INFINITY;
                if (c1 > r1) s[ni][3] = -INFINITY;
            }
        }

        // ---- online softmax (rows g and g+8; 4 lanes/row) ----
        float rm0 = -INFINITY, rm1 = -INFINITY;
#pragma unroll
        for (int ni = 0; ni < 8; ni++) {
            rm0 = fmaxf(rm0, fmaxf(s[ni][0], s[ni][1]));
            rm1 = fmaxf(rm1, fmaxf(s[ni][2], s[ni][3]));
        }
        rm0 = fmaxf(rm0, __shfl_xor_sync(0xffffffffu, rm0, 1));
        rm0 = fmaxf(rm0, __shfl_xor_sync(0xffffffffu, rm0, 2));
        rm1 = fmaxf(rm1, __shfl_xor_sync(0xffffffffu, rm1, 1));
        rm1 = fmaxf(rm1, __shfl_xor_sync(0xffffffffu, rm1, 2));
        float mn0 = fmaxf(m0, rm0), mn1 = fmaxf(m1, rm1);
        float cr0 = __expf(m0 - mn0), cr1 = __expf(m1 - mn1);
        m0 = mn0; m1 = mn1;
        float ps0 = 0.f, ps1 = 0.f;
#pragma unroll
        for (int ni = 0; ni < 8; ni++) {
            s[ni][0] = __expf(s[ni][0] - mn0);
            s[ni][1] = __expf(s[ni][1] - mn0);
            s[ni][2] = __expf(s[ni][2] - mn1);
            s[ni][3] = __expf(s[ni][3] - mn1);
            ps0 += s[ni][0] + s[ni][1];
            ps1 += s[ni][2] + s[ni][3];
        }
        ps0 += __shfl_xor_sync(0xffffffffu, ps0, 1);
        ps0 += __shfl_xor_sync(0xffffffffu, ps0, 2);
        ps1 += __shfl_xor_sync(0xffffffffu, ps1, 1);
        ps1 += __shfl_xor_sync(0xffffffffu, ps1, 2);
        l0s = l0s * cr0 + ps0;
        l1s = l1s * cr1 + ps1;
#pragma unroll
        for (int nj = 0; nj < 16; nj++) {
            o_acc[nj][0] *= cr0; o_acc[nj][1] *= cr0;
            o_acc[nj][2] *= cr1; o_acc[nj][3] *= cr1;
        }

        // ---- O += P V (bf16x3); P a-frags from score c-frags in regs ----
#pragma unroll
        for (int ks2 = 0; ks2 < 4; ks2++) {
            unsigned ph[4], pl[4];
            split2(s[2 * ks2][0],     s[2 * ks2][1],     ph[0], pl[0]);
            split2(s[2 * ks2][2],     s[2 * ks2][3],     ph[1], pl[1]);
            split2(s[2 * ks2 + 1][0], s[2 * ks2 + 1][1], ph[2], pl[2]);
            split2(s[2 * ks2 + 1][2], s[2 * ks2 + 1][3], ph[3], pl[3]);
            unsigned rowb = (unsigned)(ks2 * 16 + (lane & 15)) * (KVW * 4);
#pragma unroll
            for (int nj = 0; nj < 16; nj++) {
                unsigned v0, v1, u0, u1;
                ldsm_x2_trans(v0, v1, vbH + rowb + nj * 16);
                ldsm_x2_trans(u0, u1, vbL + rowb + nj * 16);
                mma_bf16(o_acc[nj], ph[0], ph[1], ph[2], ph[3], v0, v1);
                mma_bf16(o_acc[nj], ph[0], ph[1], ph[2], ph[3], u0, u1);
                mma_bf16(o_acc[nj], pl[0], pl[1], pl[2], pl[3], v0, v1);
            }
        }
    }

    // ---- epilogue ----
    float inv0 = 1.f / l0s, inv1 = 1.f / l1s;
    int r0 = q0 + warp * 16 + g;
    float* o0 = O + (size_t)r0 * QDIM + h * HD;
    float* o1 = o0 + 8 * QDIM;
#pragma unroll
    for (int nj = 0; nj < 16; nj++) {
        int d = nj * 8 + 2 * t;
        *(float2*)(o0 + d) = make_float2(o_acc[nj][0] * inv0, o_acc[nj][1] * inv0);
        *(float2*)(o1 + d) = make_float2(o_acc[nj][2] * inv1, o_acc[nj][3] * inv1);
    }
}

// ======================================================================
// Launch
// ======================================================================
extern "C" void kernel_launch(void* const* d_in, const int* in_sizes, int n_in,
                              void* d_out, int out_size)
{
    const float* x        = (const float*)d_in[0];
    const float* cosb     = (const float*)d_in[1];
    const float* sinb     = (const float*)d_in[2];
    const float* q_scales = (const float*)d_in[3];
    const float* q_bias   = (const float*)d_in[4];
    const float* k_scales = (const float*)d_in[5];
    const float* k_bias   = (const float*)d_in[6];
    const float* v_scales = (const float*)d_in[7];
    const float* v_bias   = (const float*)d_in[8];
    const float* o_scales = (const float*)d_in[9];
    const int* q_qweight  = (const int*)d_in[10];
    const int* q_qzeros   = (const int*)d_in[11];
    const int* k_qweight  = (const int*)d_in[12];
    const int* k_qzeros   = (const int*)d_in[13];
    const int* v_qweight  = (const int*)d_in[14];
    const int* v_qzeros   = (const int*)d_in[15];
    const int* o_qweight  = (const int*)d_in[16];
    const int* o_qzeros   = (const int*)d_in[17];
    float* out = (float*)d_out;

    float *pq, *pk, *pv, *pa;
    cudaGetSymbolAddress((void**)&pq, g_q);
    cudaGetSymbolAddress((void**)&pk, g_k);
    cudaGetSymbolAddress((void**)&pv, g_v);
    cudaGetSymbolAddress((void**)&pa, g_a);

    // QKV projections (bf16x3 tensor cores)
    {
        dim3 blk(256);
        dim3 gq(QDIM / BN, S_LEN / BM);
        gemm_q4_tc_kernel<<<gq, blk>>>(x, q_qweight, q_scales, q_qzeros, q_bias,
                                       pq, S_LEN, QDIM, HIDDEN);
        dim3 gk(KVDIM / BN, S_LEN / BM);
        gemm_q4_tc_kernel<<<gk, blk>>>(x, k_qweight, k_scales, k_qzeros, k_bias,
                                       pk, S_LEN, KVDIM, HIDDEN);
        gemm_q4_tc_kernel<<<gk, blk>>>(x, v_qweight, v_scales, v_qzeros, v_bias,
                                       pv, S_LEN, KVDIM, HIDDEN);
    }

    // RoPE in-place on Q and K
    {
        dim3 grid(NH + NKV, S_LEN);
        rope_kernel<<<grid, 64>>>(pq, pk, cosb, sinb);
    }

    // Flash attention (bf16x3 tensor cores)
    {
        size_t smem = (size_t)(4 * FPLANE) * sizeof(unsigned);   // 69632 B
        cudaFuncSetAttribute(flash_tc_kernel,
                             cudaFuncAttributeMaxDynamicSharedMemorySize, (int)smem);
        dim3 grid(S_LEN / FBQ, NH);
        flash_tc_kernel<<<grid, 256, smem>>>(pq, pk, pv, pa);
    }

    // Output projection (no bias)
    {
        dim3 blk(256);
        dim3 go(HIDDEN / BN, S_LEN / BM);
        gemm_q4_tc_kernel<<<go, blk>>>(pa, o_qweight, o_scales, o_qzeros, nullptr,
                                       out, S_LEN, HIDDEN, QDIM);
    }
}

// round 5
// speedup vs baseline: 3.0153x; 1.2326x over previous
#include <cuda_runtime.h>
#include <cuda_bf16.h>
#include <math.h>

// Problem constants
#define S_LEN 2048
#define HIDDEN 2560
#define NH 32
#define NKV 8
#define HD 128
#define QDIM (NH*HD)    // 4096
#define KVDIM (NKV*HD)  // 1024
#define GS 128

// -------- scratch (static device arrays; no allocation allowed) --------
__device__ float g_q[S_LEN * QDIM];
__device__ float g_k[S_LEN * KVDIM];
__device__ float g_v[S_LEN * KVDIM];
__device__ float g_a[S_LEN * QDIM];

// ======================================================================
// shared helpers
// ======================================================================
__device__ __forceinline__ void split2(float f0, float f1,
                                       unsigned &hi, unsigned &lo) {
    __nv_bfloat16 h0 = __float2bfloat16(f0);
    __nv_bfloat16 h1 = __float2bfloat16(f1);
    __nv_bfloat16 l0 = __float2bfloat16(f0 - __bfloat162float(h0));
    __nv_bfloat16 l1 = __float2bfloat16(f1 - __bfloat162float(h1));
    hi = (unsigned)__bfloat16_as_ushort(h0) |
         ((unsigned)__bfloat16_as_ushort(h1) << 16);
    lo = (unsigned)__bfloat16_as_ushort(l0) |
         ((unsigned)__bfloat16_as_ushort(l1) << 16);
}

__device__ __forceinline__ unsigned pack2(float f0, float f1) {
    return (unsigned)__bfloat16_as_ushort(__float2bfloat16(f0)) |
           ((unsigned)__bfloat16_as_ushort(__float2bfloat16(f1)) << 16);
}

__device__ __forceinline__ void mma_bf16(float c[4],
                                         unsigned a0, unsigned a1, unsigned a2, unsigned a3,
                                         unsigned b0, unsigned b1) {
    asm volatile(
        "mma.sync.aligned.m16n8k16.row.col.f32.bf16.bf16.f32 "
        "{%0,%1,%2,%3}, {%4,%5,%6,%7}, {%8,%9}, {%0,%1,%2,%3};"
        : "+f"(c[0]), "+f"(c[1]), "+f"(c[2]), "+f"(c[3])
        : "r"(a0), "r"(a1), "r"(a2), "r"(a3), "r"(b0), "r"(b1));
}

__device__ __forceinline__ void ldsm_x2_trans(unsigned &r0, unsigned &r1, unsigned addr) {
    asm volatile("ldmatrix.sync.aligned.m8n8.x2.trans.shared.b16 {%0,%1}, [%2];"
                 : "=r"(r0), "=r"(r1) : "r"(addr));
}

__device__ __forceinline__ unsigned smem_u32(const void* p) {
    return (unsigned)__cvta_generic_to_shared(p);
}

// ======================================================================
// Dequant GEMM v2: exact-int4 B + per-tile scale folding, bf16 MMA
//   C[M,N] = A[M,K] @ ((nib - z) * s)[K,N] (+bias)
// A split hi/lo bf16 (residual ~2^-16); B = (nib-z) EXACT in bf16.
// Per BK-tile partial folded into fp32 acc with the group's scale.
// BM=128 BN=128 BK=32, 8 warps (2x4), warp tile 64x32, double-buffered.
// ======================================================================
#define BM 128
#define BN 128
#define BK 32
#define GST 20              // padded word stride per row
#define GPL (128 * GST)     // words per plane (2560)
#define GBUF (3 * GPL)      // words per buffer (AsH, AsL, Bs)

__global__ __launch_bounds__(256, 1)
void gemm_q4_tc_kernel(const float* __restrict__ A,
                       const int*   __restrict__ qw,
                       const float* __restrict__ sc,
                       const int*   __restrict__ qz,
                       const float* __restrict__ bias,
                       float* __restrict__ C,
                       int M, int N, int K)
{
    extern __shared__ unsigned gsm[];   // 2 buffers x (AsH | AsL | Bs)

    int tid  = threadIdx.x;
    int lane = tid & 31;
    int warp = tid >> 5;
    int warp_m = warp & 1;
    int warp_n = warp >> 1;
    int bm = blockIdx.y * BM;
    int bn = blockIdx.x * BN;
    int t = lane & 3;
    int g = lane >> 2;

    // A global-load mapping: 1024 float4, 4 per thread
    int arow[4], akp[4];
#pragma unroll
    for (int i = 0; i < 4; i++) {
        int idx = tid + i * 256;
        arow[i] = idx >> 3;
        akp[i]  = (idx & 7) << 1;
    }
    // B mapping: 128 n-cols x 4 packed k-words, 2 words/thread
    int n_loc = tid & 127;
    int kp0   = (tid >> 7) << 1;

    // scale columns for this thread's c-fragments
    int scol[4];
#pragma unroll
    for (int ni = 0; ni < 4; ni++)
        scol[ni] = bn + warp_n * 32 + ni * 8 + (t << 1);

    float acc[4][4][4];
#pragma unroll
    for (int mi = 0; mi < 4; mi++)
#pragma unroll
        for (int ni = 0; ni < 4; ni++)
#pragma unroll
            for (int r = 0; r < 4; r++) acc[mi][ni][r] = 0.f;

    float sreg[4][2];

    // ---- prologue: load + store tile 0 into buffer 0 ----
    float4 aR[4];
    unsigned bw[2];
    float bz;
#pragma unroll
    for (int i = 0; i < 4; i++)
        aR[i] = *(const float4*)(A + (size_t)(bm + arow[i]) * K + (akp[i] << 1));
    {
        const int* qwp = qw + (size_t)kp0 * N + bn + n_loc;
        bw[0] = (unsigned)qwp[0];
        bw[1] = (unsigned)qwp[N];
        bz = (float)qz[bn + n_loc];
    }
    {
        unsigned* AsH = gsm;
        unsigned* AsL = gsm + GPL;
        unsigned* Bs  = gsm + 2 * GPL;
#pragma unroll
        for (int i = 0; i < 4; i++) {
            unsigned h, l;
            split2(aR[i].x, aR[i].y, h, l);
            AsH[arow[i] * GST + akp[i]]     = h;  AsL[arow[i] * GST + akp[i]]     = l;
            split2(aR[i].z, aR[i].w, h, l);
            AsH[arow[i] * GST + akp[i] + 1] = h;  AsL[arow[i] * GST + akp[i] + 1] = l;
        }
#pragma unroll
        for (int i = 0; i < 2; i++) {
            unsigned q = bw[i];
            int kpb = (kp0 + i) * 4;
#pragma unroll
            for (int j = 0; j < 4; j++)
                Bs[n_loc * GST + kpb + j] =
                    pack2((float)((q >> (8 * j)) & 15u) - bz,
                          (float)((q >> (8 * j + 4)) & 15u) - bz);
        }
    }
    __syncthreads();

    int T = K / BK;
    for (int it = 0; it < T; it++) {
        int k0 = it * BK;
        unsigned* base  = gsm + (it & 1) * GBUF;
        unsigned* nbase = gsm + ((it + 1) & 1) * GBUF;
        bool hasNext = (it + 1 < T);

        // ---- global prefetch tile it+1 ----
        if (hasNext) {
            int kn = k0 + BK;
#pragma unroll
            for (int i = 0; i < 4; i++)
                aR[i] = *(const float4*)(A + (size_t)(bm + arow[i]) * K + kn + (akp[i] << 1));
            const int* qwp = qw + (size_t)((kn >> 3) + kp0) * N + bn + n_loc;
            bw[0] = (unsigned)qwp[0];
            bw[1] = (unsigned)qwp[N];
            bz = (float)qz[(size_t)(kn >> 7) * N + bn + n_loc];
        }

        // ---- per-group scale registers ----
        if ((k0 & 127) == 0) {
            int grp = k0 >> 7;
#pragma unroll
            for (int ni = 0; ni < 4; ni++) {
                sreg[ni][0] = sc[(size_t)grp * N + scol[ni]];
                sreg[ni][1] = sc[(size_t)grp * N + scol[ni] + 1];
            }
        }

        // ---- fragment loads (both k-steps) ----
        const unsigned* AsH = base;
        const unsigned* AsL = base + GPL;
        const unsigned* Bs  = base + 2 * GPL;
        unsigned ah[2][4][4], al[2][4][4], bh[2][4][2];
#pragma unroll
        for (int ks = 0; ks < 2; ks++) {
            int kpb = ks * 8;
#pragma unroll
            for (int mi = 0; mi < 4; mi++) {
                int r = warp_m * 64 + mi * 16 + g;
                ah[ks][mi][0] = AsH[r * GST + kpb + t];
                ah[ks][mi][1] = AsH[(r + 8) * GST + kpb + t];
                ah[ks][mi][2] = AsH[r * GST + kpb + t + 4];
                ah[ks][mi][3] = AsH[(r + 8) * GST + kpb + t + 4];
                al[ks][mi][0] = AsL[r * GST + kpb + t];
                al[ks][mi][1] = AsL[(r + 8) * GST + kpb + t];
                al[ks][mi][2] = AsL[r * GST + kpb + t + 4];
                al[ks][mi][3] = AsL[(r + 8) * GST + kpb + t + 4];
            }
#pragma unroll
            for (int ni = 0; ni < 4; ni++) {
                int c = warp_n * 32 + ni * 8 + g;
                bh[ks][ni][0] = Bs[c * GST + kpb + t];
                bh[ks][ni][1] = Bs[c * GST + kpb + t + 4];
            }
        }

        // ---- MMA with software-pipelined scale fold ----
        float tmp[2][4];
#pragma unroll
        for (int u = 0; u < 16; u++) {
            int mi = u >> 2, ni = u & 3, pb = u & 1;
            tmp[pb][0] = 0.f; tmp[pb][1] = 0.f;
            tmp[pb][2] = 0.f; tmp[pb][3] = 0.f;
            mma_bf16(tmp[pb], ah[0][mi][0], ah[0][mi][1], ah[0][mi][2], ah[0][mi][3],
                     bh[0][ni][0], bh[0][ni][1]);
            mma_bf16(tmp[pb], al[0][mi][0], al[0][mi][1], al[0][mi][2], al[0][mi][3],
                     bh[0][ni][0], bh[0][ni][1]);
            mma_bf16(tmp[pb], ah[1][mi][0], ah[1][mi][1], ah[1][mi][2], ah[1][mi][3],
                     bh[1][ni][0], bh[1][ni][1]);
            mma_bf16(tmp[pb], al[1][mi][0], al[1][mi][1], al[1][mi][2], al[1][mi][3],
                     bh[1][ni][0], bh[1][ni][1]);
            if (u > 0) {
                int v = u - 1, vm = v >> 2, vn = v & 3, vb = v & 1;
                acc[vm][vn][0] += tmp[vb][0] * sreg[vn][0];
                acc[vm][vn][1] += tmp[vb][1] * sreg[vn][1];
                acc[vm][vn][2] += tmp[vb][2] * sreg[vn][0];
                acc[vm][vn][3] += tmp[vb][3] * sreg[vn][1];
            }
        }
        acc[3][3][0] += tmp[1][0] * sreg[3][0];
        acc[3][3][1] += tmp[1][1] * sreg[3][1];
        acc[3][3][2] += tmp[1][2] * sreg[3][0];
        acc[3][3][3] += tmp[1][3] * sreg[3][1];

        // ---- store prefetched tile into the other buffer ----
        if (hasNext) {
            unsigned* nAsH = nbase;
            unsigned* nAsL = nbase + GPL;
            unsigned* nBs  = nbase + 2 * GPL;
#pragma unroll
            for (int i = 0; i < 4; i++) {
                unsigned h, l;
                split2(aR[i].x, aR[i].y, h, l);
                nAsH[arow[i] * GST + akp[i]]     = h;  nAsL[arow[i] * GST + akp[i]]     = l;
                split2(aR[i].z, aR[i].w, h, l);
                nAsH[arow[i] * GST + akp[i] + 1] = h;  nAsL[arow[i] * GST + akp[i] + 1] = l;
            }
#pragma unroll
            for (int i = 0; i < 2; i++) {
                unsigned q = bw[i];
                int kpb = (kp0 + i) * 4;
#pragma unroll
                for (int j = 0; j < 4; j++)
                    nBs[n_loc * GST + kpb + j] =
                        pack2((float)((q >> (8 * j)) & 15u) - bz,
                              (float)((q >> (8 * j + 4)) & 15u) - bz);
            }
        }
        __syncthreads();
    }

    // ---- epilogue ----
#pragma unroll
    for (int ni = 0; ni < 4; ni++) {
        int n = scol[ni];
        float b0 = 0.f, b1 = 0.f;
        if (bias) { b0 = bias[n]; b1 = bias[n + 1]; }
#pragma unroll
        for (int mi = 0; mi < 4; mi++) {
            int m = bm + warp_m * 64 + mi * 16 + g;
            float2 v0 = make_float2(acc[mi][ni][0] + b0, acc[mi][ni][1] + b1);
            float2 v1 = make_float2(acc[mi][ni][2] + b0, acc[mi][ni][3] + b1);
            *(float2*)(C + (size_t)m * N + n) = v0;
            *(float2*)(C + (size_t)(m + 8) * N + n) = v1;
        }
    }
}

// ======================================================================
// RoPE (in-place), 256-thread blocks (4 heads per block)
// ======================================================================
__global__ __launch_bounds__(256)
void rope_kernel(float* __restrict__ Qb, float* __restrict__ Kb,
                 const float* __restrict__ cosb,
                 const float* __restrict__ sinb)
{
    int s = blockIdx.y;
    int h = blockIdx.x * 4 + (threadIdx.x >> 6);
    int d = threadIdx.x & 63;
    float c1 = cosb[s * HD + d];
    float s1 = sinb[s * HD + d];
    float c2 = cosb[s * HD + d + 64];
    float s2 = sinb[s * HD + d + 64];
    float* base = (h < NH) ? (Qb + (size_t)s * QDIM + h * HD)
                           : (Kb + (size_t)s * KVDIM + (h - NH) * HD);
    float x1 = base[d];
    float x2 = base[d + 64];
    base[d]      = x1 * c1 - x2 * s1;
    base[d + 64] = x2 * c2 + x1 * s2;
}

// ======================================================================
// bf16x3 tensor-core flash attention (unchanged from R4; validated)
// ======================================================================
#define FBQ 128
#define FBK 64
#define KVW 68
#define FPLANE (FBK * KVW)

__global__ __launch_bounds__(256, 1)
void flash_tc_kernel(const float* __restrict__ Q,
                     const float* __restrict__ Kb,
                     const float* __restrict__ Vb,
                     float* __restrict__ O)
{
    extern __shared__ unsigned fsm[];
    unsigned (*KsH)[KVW] = (unsigned(*)[KVW])(fsm);
    unsigned (*KsL)[KVW] = (unsigned(*)[KVW])(fsm + FPLANE);
    unsigned (*VsH)[KVW] = (unsigned(*)[KVW])(fsm + 2 * FPLANE);
    unsigned (*VsL)[KVW] = (unsigned(*)[KVW])(fsm + 3 * FPLANE);

    int h = blockIdx.y;
    int qt = gridDim.x - 1 - blockIdx.x;
    int q0 = qt * FBQ;
    int kvh = h >> 2;
    int tid = threadIdx.x, lane = tid & 31, warp = tid >> 5;
    int t = lane & 3, g = lane >> 2;

    unsigned qh[8][4], ql[8][4];
    {
        const float sc = 0.08838834764831845f;
        int r0 = q0 + warp * 16 + g;
        const float* p0 = Q + (size_t)r0 * QDIM + h * HD;
        const float* p1 = p0 + 8 * QDIM;
#pragma unroll
        for (int ks = 0; ks < 8; ks++) {
            int d = ks * 16 + 2 * t;
            float2 a0 = *(const float2*)(p0 + d);
            float2 a1 = *(const float2*)(p1 + d);
            float2 a2 = *(const float2*)(p0 + d + 8);
            float2 a3 = *(const float2*)(p1 + d + 8);
            split2(a0.x * sc, a0.y * sc, qh[ks][0], ql[ks][0]);
            split2(a1.x * sc, a1.y * sc, qh[ks][1], ql[ks][1]);
            split2(a2.x * sc, a2.y * sc, qh[ks][2], ql[ks][2]);
            split2(a3.x * sc, a3.y * sc, qh[ks][3], ql[ks][3]);
        }
    }

    float m0 = -INFINITY, m1 = -INFINITY, l0s = 0.f, l1s = 0.f;
    float o_acc[16][4];
#pragma unroll
    for (int nj = 0; nj < 16; nj++)
#pragma unroll
        for (int r = 0; r < 4; r++) o_acc[nj][r] = 0.f;

    unsigned vbH = smem_u32(VsH);
    unsigned vbL = smem_u32(VsL);

    int ntiles = (q0 + FBQ) >> 6;
    for (int tt = 0; tt < ntiles; tt++) {
        int kb = tt << 6;
        __syncthreads();
#pragma unroll
        for (int it = 0; it < 8; it++) {
            int idx = tid + it * 256;
            int r = idx >> 5;
            int c = idx & 31;
            const float* kp = Kb + (size_t)(kb + r) * KVDIM + kvh * HD + c * 4;
            float4 kv = *(const float4*)kp;
            unsigned w0, w1, w2, w3;
            split2(kv.x, kv.y, w0, w1);
            split2(kv.z, kv.w, w2, w3);
            *(uint2*)&KsH[r][c * 2] = make_uint2(w0, w2);
            *(uint2*)&KsL[r][c * 2] = make_uint2(w1, w3);
            const float* vp = Vb + (size_t)(kb + r) * KVDIM + kvh * HD + c * 4;
            float4 vv = *(const float4*)vp;
            split2(vv.x, vv.y, w0, w1);
            split2(vv.z, vv.w, w2, w3);
            *(uint2*)&VsH[r][c * 2] = make_uint2(w0, w2);
            *(uint2*)&VsL[r][c * 2] = make_uint2(w1, w3);
        }
        __syncthreads();

        float s[8][4];
#pragma unroll
        for (int ni = 0; ni < 8; ni++)
#pragma unroll
            for (int r = 0; r < 4; r++) s[ni][r] = 0.f;

#pragma unroll
        for (int ks = 0; ks < 8; ks++) {
            int w = ks * 8 + t;
#pragma unroll
            for (int ni = 0; ni < 8; ni++) {
                int col = ni * 8 + g;
                unsigned bh0 = KsH[col][w], bh1 = KsH[col][w + 4];
                unsigned bl0 = KsL[col][w], bl1 = KsL[col][w + 4];
                mma_bf16(s[ni], qh[ks][0], qh[ks][1], qh[ks][2], qh[ks][3], bh0, bh1);
                mma_bf16(s[ni], qh[ks][0], qh[ks][1], qh[ks][2], qh[ks][3], bl0, bl1);
                mma_bf16(s[ni], ql[ks][0], ql[ks][1], ql[ks][2], ql[ks][3], bh0, bh1);
            }
        }

        if (kb + FBK > q0) {
            int r0 = q0 + warp * 16 + g, r1 = r0 + 8;
#pragma unroll
            for (int ni = 0; ni < 8; ni++) {
                int c0 = kb + ni * 8 + 2 * t, c1 = c0 + 1;
                if (c0 > r0) s[ni][0] = -INFINITY;
                if (c1 > r0) s[ni][1] = -INFINITY;
                if (c0 > r1) s[ni][2] = -INFINITY;
                if (c1 > r1) s[ni][3] = -INFINITY;
            }
        }

        float rm0 = -INFINITY, rm1 = -INFINITY;
#pragma unroll
        for (int ni = 0; ni < 8; ni++) {
            rm0 = fmaxf(rm0, fmaxf(s[ni][0], s[ni][1]));
            rm1 = fmaxf(rm1, fmaxf(s[ni][2], s[ni][3]));
        }
        rm0 = fmaxf(rm0, __shfl_xor_sync(0xffffffffu, rm0, 1));
        rm0 = fmaxf(rm0, __shfl_xor_sync(0xffffffffu, rm0, 2));
        rm1 = fmaxf(rm1, __shfl_xor_sync(0xffffffffu, rm1, 1));
        rm1 = fmaxf(rm1, __shfl_xor_sync(0xffffffffu, rm1, 2));
        float mn0 = fmaxf(m0, rm0), mn1 = fmaxf(m1, rm1);
        float cr0 = __expf(m0 - mn0), cr1 = __expf(m1 - mn1);
        m0 = mn0; m1 = mn1;
        float ps0 = 0.f, ps1 = 0.f;
#pragma unroll
        for (int ni = 0; ni < 8; ni++) {
            s[ni][0] = __expf(s[ni][0] - mn0);
            s[ni][1] = __expf(s[ni][1] - mn0);
            s[ni][2] = __expf(s[ni][2] - mn1);
            s[ni][3] = __expf(s[ni][3] - mn1);
            ps0 += s[ni][0] + s[ni][1];
            ps1 += s[ni][2] + s[ni][3];
        }
        ps0 += __shfl_xor_sync(0xffffffffu, ps0, 1);
        ps0 += __shfl_xor_sync(0xffffffffu, ps0, 2);
        ps1 += __shfl_xor_sync(0xffffffffu, ps1, 1);
        ps1 += __shfl_xor_sync(0xffffffffu, ps1, 2);
        l0s = l0s * cr0 + ps0;
        l1s = l1s * cr1 + ps1;
#pragma unroll
        for (int nj = 0; nj < 16; nj++) {
            o_acc[nj][0] *= cr0; o_acc[nj][1] *= cr0;
            o_acc[nj][2] *= cr1; o_acc[nj][3] *= cr1;
        }

#pragma unroll
        for (int ks2 = 0; ks2 < 4; ks2++) {
            unsigned ph[4], pl[4];
            split2(s[2 * ks2][0],     s[2 * ks2][1],     ph[0], pl[0]);
            split2(s[2 * ks2][2],     s[2 * ks2][3],     ph[1], pl[1]);
            split2(s[2 * ks2 + 1][0], s[2 * ks2 + 1][1], ph[2], pl[2]);
            split2(s[2 * ks2 + 1][2], s[2 * ks2 + 1][3], ph[3], pl[3]);
            unsigned rowb = (unsigned)(ks2 * 16 + (lane & 15)) * (KVW * 4);
#pragma unroll
            for (int nj = 0; nj < 16; nj++) {
                unsigned v0, v1, u0, u1;
                ldsm_x2_trans(v0, v1, vbH + rowb + nj * 16);
                ldsm_x2_trans(u0, u1, vbL + rowb + nj * 16);
                mma_bf16(o_acc[nj], ph[0], ph[1], ph[2], ph[3], v0, v1);
                mma_bf16(o_acc[nj], ph[0], ph[1], ph[2], ph[3], u0, u1);
                mma_bf16(o_acc[nj], pl[0], pl[1], pl[2], pl[3], v0, v1);
            }
        }
    }

    float inv0 = 1.f / l0s, inv1 = 1.f / l1s;
    int r0 = q0 + warp * 16 + g;
    float* o0 = O + (size_t)r0 * QDIM + h * HD;
    float* o1 = o0 + 8 * QDIM;
#pragma unroll
    for (int nj = 0; nj < 16; nj++) {
        int d = nj * 8 + 2 * t;
        *(float2*)(o0 + d) = make_float2(o_acc[nj][0] * inv0, o_acc[nj][1] * inv0);
        *(float2*)(o1 + d) = make_float2(o_acc[nj][2] * inv1, o_acc[nj][3] * inv1);
    }
}

// ======================================================================
// Launch
// ======================================================================
extern "C" void kernel_launch(void* const* d_in, const int* in_sizes, int n_in,
                              void* d_out, int out_size)
{
    const float* x        = (const float*)d_in[0];
    const float* cosb     = (const float*)d_in[1];
    const float* sinb     = (const float*)d_in[2];
    const float* q_scales = (const float*)d_in[3];
    const float* q_bias   = (const float*)d_in[4];
    const float* k_scales = (const float*)d_in[5];
    const float* k_bias   = (const float*)d_in[6];
    const float* v_scales = (const float*)d_in[7];
    const float* v_bias   = (const float*)d_in[8];
    const float* o_scales = (const float*)d_in[9];
    const int* q_qweight  = (const int*)d_in[10];
    const int* q_qzeros   = (const int*)d_in[11];
    const int* k_qweight  = (const int*)d_in[12];
    const int* k_qzeros   = (const int*)d_in[13];
    const int* v_qweight  = (const int*)d_in[14];
    const int* v_qzeros   = (const int*)d_in[15];
    const int* o_qweight  = (const int*)d_in[16];
    const int* o_qzeros   = (const int*)d_in[17];
    float* out = (float*)d_out;

    float *pq, *pk, *pv, *pa;
    cudaGetSymbolAddress((void**)&pq, g_q);
    cudaGetSymbolAddress((void**)&pk, g_k);
    cudaGetSymbolAddress((void**)&pv, g_v);
    cudaGetSymbolAddress((void**)&pa, g_a);

    size_t gsmem = (size_t)(2 * GBUF) * sizeof(unsigned);   // 61440 B
    cudaFuncSetAttribute(gemm_q4_tc_kernel,
                         cudaFuncAttributeMaxDynamicSharedMemorySize, (int)gsmem);

    // QKV projections
    {
        dim3 blk(256);
        dim3 gq(QDIM / BN, S_LEN / BM);
        gemm_q4_tc_kernel<<<gq, blk, gsmem>>>(x, q_qweight, q_scales, q_qzeros, q_bias,
                                              pq, S_LEN, QDIM, HIDDEN);
        dim3 gk(KVDIM / BN, S_LEN / BM);
        gemm_q4_tc_kernel<<<gk, blk, gsmem>>>(x, k_qweight, k_scales, k_qzeros, k_bias,
                                              pk, S_LEN, KVDIM, HIDDEN);
        gemm_q4_tc_kernel<<<gk, blk, gsmem>>>(x, v_qweight, v_scales, v_qzeros, v_bias,
                                              pv, S_LEN, KVDIM, HIDDEN);
    }

    // RoPE in-place on Q and K
    {
        dim3 grid((NH + NKV) / 4, S_LEN);
        rope_kernel<<<grid, 256>>>(pq, pk, cosb, sinb);
    }

    // Flash attention
    {
        size_t smem = (size_t)(4 * FPLANE) * sizeof(unsigned);
        cudaFuncSetAttribute(flash_tc_kernel,
                             cudaFuncAttributeMaxDynamicSharedMemorySize, (int)smem);
        dim3 grid(S_LEN / FBQ, NH);
        flash_tc_kernel<<<grid, 256, smem>>>(pq, pk, pv, pa);
    }

    // Output projection (no bias)
    {
        dim3 blk(256);
        dim3 go(HIDDEN / BN, S_LEN / BM);
        gemm_q4_tc_kernel<<<go, blk, gsmem>>>(pa, o_qweight, o_scales, o_qzeros, nullptr,
                                              out, S_LEN, HIDDEN, QDIM);
    }
}

// round 7
// speedup vs baseline: 3.1723x; 1.0521x over previous
#include <cuda_runtime.h>
#include <cuda_bf16.h>
#include <math.h>

// Problem constants
#define S_LEN 2048
#define HIDDEN 2560
#define NH 32
#define NKV 8
#define HD 128
#define QDIM (NH*HD)    // 4096
#define KVDIM (NKV*HD)  // 1024
#define GS 128

// -------- scratch (static device arrays; no allocation allowed) --------
__device__ float g_q[S_LEN * QDIM];            // Q fp32 (roped in-place)
__device__ float g_k[S_LEN * KVDIM];           // K fp32 (pre-rope)
__device__ float g_v[S_LEN * KVDIM];           // V fp32
__device__ __nv_bfloat16 g_xh[S_LEN * HIDDEN], g_xl[S_LEN * HIDDEN];
__device__ __nv_bfloat16 g_kh[S_LEN * KVDIM], g_kl[S_LEN * KVDIM];
__device__ __nv_bfloat16 g_vh[S_LEN * KVDIM], g_vl[S_LEN * KVDIM];
__device__ __nv_bfloat16 g_ah[S_LEN * QDIM],  g_al[S_LEN * QDIM];

// ======================================================================
// helpers
// ======================================================================
__device__ __forceinline__ void split2(float f0, float f1,
                                       unsigned &hi, unsigned &lo) {
    __nv_bfloat16 h0 = __float2bfloat16(f0);
    __nv_bfloat16 h1 = __float2bfloat16(f1);
    __nv_bfloat16 l0 = __float2bfloat16(f0 - __bfloat162float(h0));
    __nv_bfloat16 l1 = __float2bfloat16(f1 - __bfloat162float(h1));
    hi = (unsigned)__bfloat16_as_ushort(h0) |
         ((unsigned)__bfloat16_as_ushort(h1) << 16);
    lo = (unsigned)__bfloat16_as_ushort(l0) |
         ((unsigned)__bfloat16_as_ushort(l1) << 16);
}

__device__ __forceinline__ unsigned pack2(float f0, float f1) {
    return (unsigned)__bfloat16_as_ushort(__float2bfloat16(f0)) |
           ((unsigned)__bfloat16_as_ushort(__float2bfloat16(f1)) << 16);
}

__device__ __forceinline__ void mma_bf16(float c[4],
                                         unsigned a0, unsigned a1, unsigned a2, unsigned a3,
                                         unsigned b0, unsigned b1) {
    asm volatile(
        "mma.sync.aligned.m16n8k16.row.col.f32.bf16.bf16.f32 "
        "{%0,%1,%2,%3}, {%4,%5,%6,%7}, {%8,%9}, {%0,%1,%2,%3};"
        : "+f"(c[0]), "+f"(c[1]), "+f"(c[2]), "+f"(c[3])
        : "r"(a0), "r"(a1), "r"(a2), "r"(a3), "r"(b0), "r"(b1));
}

__device__ __forceinline__ void ldsm_x2_trans(unsigned &r0, unsigned &r1, unsigned addr) {
    asm volatile("ldmatrix.sync.aligned.m8n8.x2.trans.shared.b16 {%0,%1}, [%2];"
                 : "=r"(r0), "=r"(r1) : "r"(addr));
}

__device__ __forceinline__ unsigned smem_u32(const void* p) {
    return (unsigned)__cvta_generic_to_shared(p);
}

__device__ __forceinline__ void cp_async16(unsigned dst, const void* src) {
    asm volatile("cp.async.cg.shared.global [%0], [%1], 16;" :: "r"(dst), "l"(src));
}
#define CP_COMMIT() asm volatile("cp.async.commit_group;" ::: "memory")
#define CP_WAIT0()  asm volatile("cp.async.wait_group 0;" ::: "memory")

// ======================================================================
// presplit: x fp32 -> bf16 hi/lo planes
// ======================================================================
__global__ __launch_bounds__(256)
void presplit_kernel(const float* __restrict__ x,
                     __nv_bfloat16* __restrict__ xh,
                     __nv_bfloat16* __restrict__ xl)
{
    int i = blockIdx.x * 256 + threadIdx.x;   // pair index
    float2 v = ((const float2*)x)[i];
    unsigned h, l;
    split2(v.x, v.y, h, l);
    ((unsigned*)xh)[i] = h;
    ((unsigned*)xl)[i] = l;
}

// ======================================================================
// Dequant GEMM v3: presplit A (cp.async) + exact-int4 B + scale folding
// A planes bf16 [M][K]; B = (nib-z) exact bf16; fold scale per BK tile.
// BM=128 BN=128 BK=32, 8 warps (2x4), warp tile 64x32, double-buffered.
// ======================================================================
#define BM 128
#define BN 128
#define BK 32
#define GST 20              // padded word stride per row
#define GPL (128 * GST)     // words per plane (2560)
#define GBUF (3 * GPL)      // words per buffer (AsH | AsL | Bs)

__global__ __launch_bounds__(256)
void gemm_q4_tc_kernel(const __nv_bfloat16* __restrict__ Ahp,
                       const __nv_bfloat16* __restrict__ Alp,
                       const int*   __restrict__ qw,
                       const float* __restrict__ sc,
                       const int*   __restrict__ qz,
                       const float* __restrict__ bias,
                       float* __restrict__ C,
                       int M, int N, int K)
{
    extern __shared__ unsigned gsm[];
    unsigned sbase = smem_u32(gsm);

    int tid  = threadIdx.x;
    int lane = tid & 31;
    int warp = tid >> 5;
    int warp_m = warp & 1;
    int warp_n = warp >> 1;
    int bm = blockIdx.y * BM;
    int bn = blockIdx.x * BN;
    int t = lane & 3;
    int g = lane >> 2;

    // A cp.async mapping: 512 chunks of 16B per plane; c = tid, tid+256
    int am[2], ach[2];
#pragma unroll
    for (int i = 0; i < 2; i++) {
        int c = tid + i * 256;
        am[i]  = c >> 2;
        ach[i] = c & 3;
    }
    // B mapping: 128 n-cols x 4 packed k-words, 2 words/thread
    int n_loc = tid & 127;
    int kp0   = (tid >> 7) << 1;

    int scol[4];
#pragma unroll
    for (int ni = 0; ni < 4; ni++)
        scol[ni] = bn + warp_n * 32 + ni * 8 + (t << 1);

    float acc[4][4][4];
#pragma unroll
    for (int mi = 0; mi < 4; mi++)
#pragma unroll
        for (int ni = 0; ni < 4; ni++)
#pragma unroll
            for (int r = 0; r < 4; r++) acc[mi][ni][r] = 0.f;

    float sreg[4][2];
    unsigned bw[2];
    float bz;

    int T = K / BK;

    // ---- prologue: A tile0 via cp.async, B tile0 via regs ----
    {
        unsigned b0 = sbase;
#pragma unroll
        for (int i = 0; i < 2; i++) {
            const __nv_bfloat16* sh = Ahp + (size_t)(bm + am[i]) * K + ach[i] * 8;
            const __nv_bfloat16* sl = Alp + (size_t)(bm + am[i]) * K + ach[i] * 8;
            unsigned d = (unsigned)(am[i] * GST + ach[i] * 4) * 4;
            cp_async16(b0 + d, sh);
            cp_async16(b0 + GPL * 4 + d, sl);
        }
        CP_COMMIT();
        const int* qp = qw + (size_t)kp0 * N + bn + n_loc;
        bw[0] = (unsigned)qp[0];
        bw[1] = (unsigned)qp[N];
        bz = (float)qz[bn + n_loc];
        unsigned* Bs = gsm + 2 * GPL;
#pragma unroll
        for (int i = 0; i < 2; i++) {
            unsigned q = bw[i];
            int kpb = (kp0 + i) * 4;
#pragma unroll
            for (int j = 0; j < 4; j++)
                Bs[n_loc * GST + kpb + j] =
                    pack2((float)((q >> (8 * j)) & 15u) - bz,
                          (float)((q >> (8 * j + 4)) & 15u) - bz);
        }
        if (T > 1) {   // stage B tile1
            const int* qp1 = qw + (size_t)(4 + kp0) * N + bn + n_loc;
            bw[0] = (unsigned)qp1[0];
            bw[1] = (unsigned)qp1[N];
            bz = (float)qz[(size_t)(BK >> 7) * N + bn + n_loc];
        }
        CP_WAIT0();
        __syncthreads();
    }

    for (int it = 0; it < T; it++) {
        int k0 = it * BK;
        int b = it & 1;
        unsigned* base = gsm + b * GBUF;
        bool hasNext = (it + 1 < T);

        // ---- prefetch tile it+1 into other buffer ----
        if (hasNext) {
            int kn = k0 + BK;
            unsigned nb = sbase + ((b ^ 1) * GBUF) * 4;
#pragma unroll
            for (int i = 0; i < 2; i++) {
                const __nv_bfloat16* sh = Ahp + (size_t)(bm + am[i]) * K + kn + ach[i] * 8;
                const __nv_bfloat16* sl = Alp + (size_t)(bm + am[i]) * K + kn + ach[i] * 8;
                unsigned d = (unsigned)(am[i] * GST + ach[i] * 4) * 4;
                cp_async16(nb + d, sh);
                cp_async16(nb + GPL * 4 + d, sl);
            }
            CP_COMMIT();
            unsigned* nBs = gsm + (b ^ 1) * GBUF + 2 * GPL;
#pragma unroll
            for (int i = 0; i < 2; i++) {
                unsigned q = bw[i];
                int kpb = (kp0 + i) * 4;
#pragma unroll
                for (int j = 0; j < 4; j++)
                    nBs[n_loc * GST + kpb + j] =
                        pack2((float)((q >> (8 * j)) & 15u) - bz,
                              (float)((q >> (8 * j + 4)) & 15u) - bz);
            }
            if (it + 2 < T) {
                int kn2 = k0 + 2 * BK;
                const int* qp = qw + (size_t)((kn2 >> 3) + kp0) * N + bn + n_loc;
                bw[0] = (unsigned)qp[0];
                bw[1] = (unsigned)qp[N];
                bz = (float)qz[(size_t)(kn2 >> 7) * N + bn + n_loc];
            }
        }

        // ---- per-group scale registers ----
        if ((k0 & 127) == 0) {
            int grp = k0 >> 7;
#pragma unroll
            for (int ni = 0; ni < 4; ni++) {
                sreg[ni][0] = sc[(size_t)grp * N + scol[ni]];
                sreg[ni][1] = sc[(size_t)grp * N + scol[ni] + 1];
            }
        }

        // ---- fragment loads ----
        const unsigned* AsH = base;
        const unsigned* AsL = base + GPL;
        const unsigned* Bs  = base + 2 * GPL;
        unsigned ah[2][4][4], al[2][4][4], bh[2][4][2];
#pragma unroll
        for (int ks = 0; ks < 2; ks++) {
            int kpb = ks * 8;
#pragma unroll
            for (int mi = 0; mi < 4; mi++) {
                int r = warp_m * 64 + mi * 16 + g;
                ah[ks][mi][0] = AsH[r * GST + kpb + t];
                ah[ks][mi][1] = AsH[(r + 8) * GST + kpb + t];
                ah[ks][mi][2] = AsH[r * GST + kpb + t + 4];
                ah[ks][mi][3] = AsH[(r + 8) * GST + kpb + t + 4];
                al[ks][mi][0] = AsL[r * GST + kpb + t];
                al[ks][mi][1] = AsL[(r + 8) * GST + kpb + t];
                al[ks][mi][2] = AsL[r * GST + kpb + t + 4];
                al[ks][mi][3] = AsL[(r + 8) * GST + kpb + t + 4];
            }
#pragma unroll
            for (int ni = 0; ni < 4; ni++) {
                int c = warp_n * 32 + ni * 8 + g;
                bh[ks][ni][0] = Bs[c * GST + kpb + t];
                bh[ks][ni][1] = Bs[c * GST + kpb + t + 4];
            }
        }

        // ---- MMA with software-pipelined scale fold ----
        float tmp[2][4];
#pragma unroll
        for (int u = 0; u < 16; u++) {
            int mi = u >> 2, ni = u & 3, pb = u & 1;
            tmp[pb][0] = 0.f; tmp[pb][1] = 0.f;
            tmp[pb][2] = 0.f; tmp[pb][3] = 0.f;
            mma_bf16(tmp[pb], ah[0][mi][0], ah[0][mi][1], ah[0][mi][2], ah[0][mi][3],
                     bh[0][ni][0], bh[0][ni][1]);
            mma_bf16(tmp[pb], al[0][mi][0], al[0][mi][1], al[0][mi][2], al[0][mi][3],
                     bh[0][ni][0], bh[0][ni][1]);
            mma_bf16(tmp[pb], ah[1][mi][0], ah[1][mi][1], ah[1][mi][2], ah[1][mi][3],
                     bh[1][ni][0], bh[1][ni][1]);
            mma_bf16(tmp[pb], al[1][mi][0], al[1][mi][1], al[1][mi][2], al[1][mi][3],
                     bh[1][ni][0], bh[1][ni][1]);
            if (u > 0) {
                int v = u - 1, vm = v >> 2, vn = v & 3, vb = v & 1;
                acc[vm][vn][0] += tmp[vb][0] * sreg[vn][0];
                acc[vm][vn][1] += tmp[vb][1] * sreg[vn][1];
                acc[vm][vn][2] += tmp[vb][2] * sreg[vn][0];
                acc[vm][vn][3] += tmp[vb][3] * sreg[vn][1];
            }
        }
        acc[3][3][0] += tmp[1][0] * sreg[3][0];
        acc[3][3][1] += tmp[1][1] * sreg[3][1];
        acc[3][3][2] += tmp[1][2] * sreg[3][0];
        acc[3][3][3] += tmp[1][3] * sreg[3][1];

        if (hasNext) CP_WAIT0();
        __syncthreads();
    }

    // ---- epilogue ----
#pragma unroll
    for (int ni = 0; ni < 4; ni++) {
        int n = scol[ni];
        float b0 = 0.f, b1 = 0.f;
        if (bias) { b0 = bias[n]; b1 = bias[n + 1]; }
#pragma unroll
        for (int mi = 0; mi < 4; mi++) {
            int m = bm + warp_m * 64 + mi * 16 + g;
            float2 v0 = make_float2(acc[mi][ni][0] + b0, acc[mi][ni][1] + b1);
            float2 v1 = make_float2(acc[mi][ni][2] + b0, acc[mi][ni][3] + b1);
            *(float2*)(C + (size_t)m * N + n) = v0;
            *(float2*)(C + (size_t)(m + 8) * N + n) = v1;
        }
    }
}

// ======================================================================
// RoPE + split: Q roped in-place (fp32); K roped -> bf16 hi/lo planes;
// V -> bf16 hi/lo planes. 48 logical heads, 4 per 256-thread block.
// ======================================================================
__global__ __launch_bounds__(256)
void rope_split_kernel(float* __restrict__ Qb,
                       const float* __restrict__ Kf,
                       const float* __restrict__ Vf,
                       __nv_bfloat16* __restrict__ Kh, __nv_bfloat16* __restrict__ Kl,
                       __nv_bfloat16* __restrict__ Vh, __nv_bfloat16* __restrict__ Vl,
                       const float* __restrict__ cosb,
                       const float* __restrict__ sinb)
{
    int s = blockIdx.y;
    int h = blockIdx.x * 4 + (threadIdx.x >> 6);
    int d = threadIdx.x & 63;

    if (h < NH) {
        float c1 = cosb[s * HD + d],     s1 = sinb[s * HD + d];
        float c2 = cosb[s * HD + d + 64], s2 = sinb[s * HD + d + 64];
        float* base = Qb + (size_t)s * QDIM + h * HD;
        float x1 = base[d], x2 = base[d + 64];
        base[d]      = x1 * c1 - x2 * s1;
        base[d + 64] = x2 * c2 + x1 * s2;
    } else if (h < NH + NKV) {
        int kh = h - NH;
        float c1 = cosb[s * HD + d],     s1 = sinb[s * HD + d];
        float c2 = cosb[s * HD + d + 64], s2 = sinb[s * HD + d + 64];
        const float* base = Kf + (size_t)s * KVDIM + kh * HD;
        float x1 = base[d], x2 = base[d + 64];
        float y1 = x1 * c1 - x2 * s1;
        float y2 = x2 * c2 + x1 * s2;
        size_t o = (size_t)s * KVDIM + kh * HD + d;
        __nv_bfloat16 h1 = __float2bfloat16(y1);
        __nv_bfloat16 h2 = __float2bfloat16(y2);
        Kh[o] = h1;       Kl[o] = __float2bfloat16(y1 - __bfloat162float(h1));
        Kh[o + 64] = h2;  Kl[o + 64] = __float2bfloat16(y2 - __bfloat162float(h2));
    } else {
        int vh = h - NH - NKV;
        const float* base = Vf + (size_t)s * KVDIM + vh * HD;
        float x1 = base[d], x2 = base[d + 64];
        size_t o = (size_t)s * KVDIM + vh * HD + d;
        __nv_bfloat16 h1 = __float2bfloat16(x1);
        __nv_bfloat16 h2 = __float2bfloat16(x2);
        Vh[o] = h1;       Vl[o] = __float2bfloat16(x1 - __bfloat162float(h1));
        Vh[o + 64] = h2;  Vl[o + 64] = __float2bfloat16(x2 - __bfloat162float(h2));
    }
}

// ======================================================================
// bf16x3 flash attention; K/V from presplit planes via cp.async.
// Output written as bf16 hi/lo planes for the O projection.
// ======================================================================
#define FBQ 128
#define FBK 64
#define KVW 68
#define FPLANE (FBK * KVW)

__global__ __launch_bounds__(256, 1)
void flash_tc_kernel(const float* __restrict__ Q,
                     const __nv_bfloat16* __restrict__ Kh,
                     const __nv_bfloat16* __restrict__ Kl,
                     const __nv_bfloat16* __restrict__ Vh,
                     const __nv_bfloat16* __restrict__ Vl,
                     __nv_bfloat16* __restrict__ Oh,
                     __nv_bfloat16* __restrict__ Ol)
{
    extern __shared__ unsigned fsm[];
    unsigned (*KsH)[KVW] = (unsigned(*)[KVW])(fsm);
    unsigned (*KsL)[KVW] = (unsigned(*)[KVW])(fsm + FPLANE);
    unsigned (*VsH)[KVW] = (unsigned(*)[KVW])(fsm + 2 * FPLANE);
    unsigned (*VsL)[KVW] = (unsigned(*)[KVW])(fsm + 3 * FPLANE);

    int h = blockIdx.y;
    int qt = gridDim.x - 1 - blockIdx.x;
    int q0 = qt * FBQ;
    int kvh = h >> 2;
    int tid = threadIdx.x, lane = tid & 31, warp = tid >> 5;
    int t = lane & 3, g = lane >> 2;

    unsigned kbH = smem_u32(KsH), kbL = smem_u32(KsL);
    unsigned vbH = smem_u32(VsH), vbL = smem_u32(VsL);

    // ---- Q fragments, scale folded, split hi/lo (regs) ----
    unsigned qh[8][4], ql[8][4];
    {
        const float sc = 0.08838834764831845f;
        int r0 = q0 + warp * 16 + g;
        const float* p0 = Q + (size_t)r0 * QDIM + h * HD;
        const float* p1 = p0 + 8 * QDIM;
#pragma unroll
        for (int ks = 0; ks < 8; ks++) {
            int d = ks * 16 + 2 * t;
            float2 a0 = *(const float2*)(p0 + d);
            float2 a1 = *(const float2*)(p1 + d);
            float2 a2 = *(const float2*)(p0 + d + 8);
            float2 a3 = *(const float2*)(p1 + d + 8);
            split2(a0.x * sc, a0.y * sc, qh[ks][0], ql[ks][0]);
            split2(a1.x * sc, a1.y * sc, qh[ks][1], ql[ks][1]);
            split2(a2.x * sc, a2.y * sc, qh[ks][2], ql[ks][2]);
            split2(a3.x * sc, a3.y * sc, qh[ks][3], ql[ks][3]);
        }
    }

    float m0 = -INFINITY, m1 = -INFINITY, l0s = 0.f, l1s = 0.f;
    float o_acc[16][4];
#pragma unroll
    for (int nj = 0; nj < 16; nj++)
#pragma unroll
        for (int r = 0; r < 4; r++) o_acc[nj][r] = 0.f;

    int ntiles = (q0 + FBQ) >> 6;
    for (int tt = 0; tt < ntiles; tt++) {
        int kb = tt << 6;
        __syncthreads();
        // ---- cp.async K/V tiles from presplit planes ----
#pragma unroll
        for (int i = 0; i < 4; i++) {
            int idx = tid + i * 256;
            int r = idx >> 4;              // token 0..63
            int ch = idx & 15;             // 16B chunk (8 bf16)
            size_t off = (size_t)(kb + r) * KVDIM + kvh * HD + ch * 8;
            unsigned d = (unsigned)(r * KVW + ch * 4) * 4;
            cp_async16(kbH + d, Kh + off);
            cp_async16(kbL + d, Kl + off);
            cp_async16(vbH + d, Vh + off);
            cp_async16(vbL + d, Vl + off);
        }
        CP_COMMIT();
        CP_WAIT0();
        __syncthreads();

        // ---- scores S = Q K^T (bf16x3) ----
        float s[8][4];
#pragma unroll
        for (int ni = 0; ni < 8; ni++)
#pragma unroll
            for (int r = 0; r < 4; r++) s[ni][r] = 0.f;

#pragma unroll
        for (int ks = 0; ks < 8; ks++) {
            int w = ks * 8 + t;
#pragma unroll
            for (int ni = 0; ni < 8; ni++) {
                int col = ni * 8 + g;
                unsigned bh0 = KsH[col][w], bh1 = KsH[col][w + 4];
                unsigned bl0 = KsL[col][w], bl1 = KsL[col][w + 4];
                mma_bf16(s[ni], qh[ks][0], qh[ks][1], qh[ks][2], qh[ks][3], bh0, bh1);
                mma_bf16(s[ni], qh[ks][0], qh[ks][1], qh[ks][2], qh[ks][3], bl0, bl1);
                mma_bf16(s[ni], ql[ks][0], ql[ks][1], ql[ks][2], ql[ks][3], bh0, bh1);
            }
        }

        if (kb + FBK > q0) {
            int r0 = q0 + warp * 16 + g, r1 = r0 + 8;
#pragma unroll
            for (int ni = 0; ni < 8; ni++) {
                int c0 = kb + ni * 8 + 2 * t, c1 = c0 + 1;
                if (c0 > r0) s[ni][0] = -INFINITY;
                if (c1 > r0) s[ni][1] = -INFINITY;
                if (c0 > r1) s[ni][2] = -INFINITY;
                if (c1 > r1) s[ni][3] = -INFINITY;
            }
        }

        float rm0 = -INFINITY, rm1 = -INFINITY;
#pragma unroll
        for (int ni = 0; ni < 8; ni++) {
            rm0 = fmaxf(rm0, fmaxf(s[ni][0], s[ni][1]));
            rm1 = fmaxf(rm1, fmaxf(s[ni][2], s[ni][3]));
        }
        rm0 = fmaxf(rm0, __shfl_xor_sync(0xffffffffu, rm0, 1));
        rm0 = fmaxf(rm0, __shfl_xor_sync(0xffffffffu, rm0, 2));
        rm1 = fmaxf(rm1, __shfl_xor_sync(0xffffffffu, rm1, 1));
        rm1 = fmaxf(rm1, __shfl_xor_sync(0xffffffffu, rm1, 2));
        float mn0 = fmaxf(m0, rm0), mn1 = fmaxf(m1, rm1);
        float cr0 = __expf(m0 - mn0), cr1 = __expf(m1 - mn1);
        m0 = mn0; m1 = mn1;
        float ps0 = 0.f, ps1 = 0.f;
#pragma unroll
        for (int ni = 0; ni < 8; ni++) {
            s[ni][0] = __expf(s[ni][0] - mn0);
            s[ni][1] = __expf(s[ni][1] - mn0);
            s[ni][2] = __expf(s[ni][2] - mn1);
            s[ni][3] = __expf(s[ni][3] - mn1);
            ps0 += s[ni][0] + s[ni][1];
            ps1 += s[ni][2] + s[ni][3];
        }
        ps0 += __shfl_xor_sync(0xffffffffu, ps0, 1);
        ps0 += __shfl_xor_sync(0xffffffffu, ps0, 2);
        ps1 += __shfl_xor_sync(0xffffffffu, ps1, 1);
        ps1 += __shfl_xor_sync(0xffffffffu, ps1, 2);
        l0s = l0s * cr0 + ps0;
        l1s = l1s * cr1 + ps1;
#pragma unroll
        for (int nj = 0; nj < 16; nj++) {
            o_acc[nj][0] *= cr0; o_acc[nj][1] *= cr0;
            o_acc[nj][2] *= cr1; o_acc[nj][3] *= cr1;
        }

#pragma unroll
        for (int ks2 = 0; ks2 < 4; ks2++) {
            unsigned ph[4], pl[4];
            split2(s[2 * ks2][0],     s[2 * ks2][1],     ph[0], pl[0]);
            split2(s[2 * ks2][2],     s[2 * ks2][3],     ph[1], pl[1]);
            split2(s[2 * ks2 + 1][0], s[2 * ks2 + 1][1], ph[2], pl[2]);
            split2(s[2 * ks2 + 1][2], s[2 * ks2 + 1][3], ph[3], pl[3]);
            unsigned rowb = (unsigned)(ks2 * 16 + (lane & 15)) * (KVW * 4);
#pragma unroll
            for (int nj = 0; nj < 16; nj++) {
                unsigned v0, v1, u0, u1;
                ldsm_x2_trans(v0, v1, vbH + rowb + nj * 16);
                ldsm_x2_trans(u0, u1, vbL + rowb + nj * 16);
                mma_bf16(o_acc[nj], ph[0], ph[1], ph[2], ph[3], v0, v1);
                mma_bf16(o_acc[nj], ph[0], ph[1], ph[2], ph[3], u0, u1);
                mma_bf16(o_acc[nj], pl[0], pl[1], pl[2], pl[3], v0, v1);
            }
        }
    }

    // ---- epilogue: write bf16 hi/lo planes ----
    float inv0 = 1.f / l0s, inv1 = 1.f / l1s;
    int r0 = q0 + warp * 16 + g;
    size_t b0 = (size_t)r0 * QDIM + h * HD;
    size_t b1 = b0 + 8 * (size_t)QDIM;
#pragma unroll
    for (int nj = 0; nj < 16; nj++) {
        int d = nj * 8 + 2 * t;
        unsigned hh, ll;
        split2(o_acc[nj][0] * inv0, o_acc[nj][1] * inv0, hh, ll);
        *(unsigned*)(Oh + b0 + d) = hh;
        *(unsigned*)(Ol + b0 + d) = ll;
        split2(o_acc[nj][2] * inv1, o_acc[nj][3] * inv1, hh, ll);
        *(unsigned*)(Oh + b1 + d) = hh;
        *(unsigned*)(Ol + b1 + d) = ll;
    }
}

// ======================================================================
// Launch
// ======================================================================
extern "C" void kernel_launch(void* const* d_in, const int* in_sizes, int n_in,
                              void* d_out, int out_size)
{
    const float* x        = (const float*)d_in[0];
    const float* cosb     = (const float*)d_in[1];
    const float* sinb     = (const float*)d_in[2];
    const float* q_scales = (const float*)d_in[3];
    const float* q_bias   = (const float*)d_in[4];
    const float* k_scales = (const float*)d_in[5];
    const float* k_bias   = (const float*)d_in[6];
    const float* v_scales = (const float*)d_in[7];
    const float* v_bias   = (const float*)d_in[8];
    const float* o_scales = (const float*)d_in[9];
    const int* q_qweight  = (const int*)d_in[10];
    const int* q_qzeros   = (const int*)d_in[11];
    const int* k_qweight  = (const int*)d_in[12];
    const int* k_qzeros   = (const int*)d_in[13];
    const int* v_qweight  = (const int*)d_in[14];
    const int* v_qzeros   = (const int*)d_in[15];
    const int* o_qweight  = (const int*)d_in[16];
    const int* o_qzeros   = (const int*)d_in[17];
    float* out = (float*)d_out;

    float *pq, *pk, *pv;
    __nv_bfloat16 *pxh, *pxl, *pkh, *pkl, *pvh, *pvl, *pah, *pal;
    cudaGetSymbolAddress((void**)&pq, g_q);
    cudaGetSymbolAddress((void**)&pk, g_k);
    cudaGetSymbolAddress((void**)&pv, g_v);
    cudaGetSymbolAddress((void**)&pxh, g_xh);
    cudaGetSymbolAddress((void**)&pxl, g_xl);
    cudaGetSymbolAddress((void**)&pkh, g_kh);
    cudaGetSymbolAddress((void**)&pkl, g_kl);
    cudaGetSymbolAddress((void**)&pvh, g_vh);
    cudaGetSymbolAddress((void**)&pvl, g_vl);
    cudaGetSymbolAddress((void**)&pah, g_ah);
    cudaGetSymbolAddress((void**)&pal, g_al);

    size_t gsmem = (size_t)(2 * GBUF) * sizeof(unsigned);   // 61440 B
    cudaFuncSetAttribute(gemm_q4_tc_kernel,
                         cudaFuncAttributeMaxDynamicSharedMemorySize, (int)gsmem);

    // presplit x
    presplit_kernel<<<(S_LEN * HIDDEN / 2) / 256, 256>>>(x, pxh, pxl);

    // QKV projections
    {
        dim3 blk(256);
        dim3 gq(QDIM / BN, S_LEN / BM);
        gemm_q4_tc_kernel<<<gq, blk, gsmem>>>(pxh, pxl, q_qweight, q_scales, q_qzeros,
                                              q_bias, pq, S_LEN, QDIM, HIDDEN);
        dim3 gk(KVDIM / BN, S_LEN / BM);
        gemm_q4_tc_kernel<<<gk, blk, gsmem>>>(pxh, pxl, k_qweight, k_scales, k_qzeros,
                                              k_bias, pk, S_LEN, KVDIM, HIDDEN);
        gemm_q4_tc_kernel<<<gk, blk, gsmem>>>(pxh, pxl, v_qweight, v_scales, v_qzeros,
                                              v_bias, pv, S_LEN, KVDIM, HIDDEN);
    }

    // RoPE (Q in-place) + K/V presplit
    {
        dim3 grid(12, S_LEN);
        rope_split_kernel<<<grid, 256>>>(pq, pk, pv, pkh, pkl, pvh, pvl, cosb, sinb);
    }

    // Flash attention
    {
        size_t smem = (size_t)(4 * FPLANE) * sizeof(unsigned);
        cudaFuncSetAttribute(flash_tc_kernel,
                             cudaFuncAttributeMaxDynamicSharedMemorySize, (int)smem);
        dim3 grid(S_LEN / FBQ, NH);
        flash_tc_kernel<<<grid, 256, smem>>>(pq, pkh, pkl, pvh, pvl, pah, pal);
    }

    // O projection
    {
        dim3 blk(256);
        dim3 go(HIDDEN / BN, S_LEN / BM);
        gemm_q4_tc_kernel<<<go, blk, gsmem>>>(pah, pal, o_qweight, o_scales, o_qzeros,
                                              nullptr, out, S_LEN, HIDDEN, QDIM);
    }
}

// round 8
// speedup vs baseline: 3.7611x; 1.1856x over previous
#include <cuda_runtime.h>
#include <cuda_bf16.h>
#include <math.h>

// Problem constants
#define S_LEN 2048
#define HIDDEN 2560
#define NH 32
#define NKV 8
#define HD 128
#define QDIM (NH*HD)    // 4096
#define KVDIM (NKV*HD)  // 1024
#define GS 128

// -------- scratch (static device arrays; no allocation allowed) --------
__device__ float g_q[S_LEN * QDIM];            // Q fp32 (roped in-place)
__device__ float g_k[S_LEN * KVDIM];           // K fp32 (pre-rope)
__device__ float g_v[S_LEN * KVDIM];           // V fp32
__device__ __nv_bfloat16 g_xh[S_LEN * HIDDEN], g_xl[S_LEN * HIDDEN];
__device__ __nv_bfloat16 g_kh[S_LEN * KVDIM], g_kl[S_LEN * KVDIM];
__device__ __nv_bfloat16 g_vh[S_LEN * KVDIM], g_vl[S_LEN * KVDIM];
__device__ __nv_bfloat16 g_ah[S_LEN * QDIM],  g_al[S_LEN * QDIM];

// ======================================================================
// helpers
// ======================================================================
__device__ __forceinline__ void split2(float f0, float f1,
                                       unsigned &hi, unsigned &lo) {
    __nv_bfloat16 h0 = __float2bfloat16(f0);
    __nv_bfloat16 h1 = __float2bfloat16(f1);
    __nv_bfloat16 l0 = __float2bfloat16(f0 - __bfloat162float(h0));
    __nv_bfloat16 l1 = __float2bfloat16(f1 - __bfloat162float(h1));
    hi = (unsigned)__bfloat16_as_ushort(h0) |
         ((unsigned)__bfloat16_as_ushort(h1) << 16);
    lo = (unsigned)__bfloat16_as_ushort(l0) |
         ((unsigned)__bfloat16_as_ushort(l1) << 16);
}

__device__ __forceinline__ unsigned pack2(float f0, float f1) {
    return (unsigned)__bfloat16_as_ushort(__float2bfloat16(f0)) |
           ((unsigned)__bfloat16_as_ushort(__float2bfloat16(f1)) << 16);
}

__device__ __forceinline__ void mma_bf16(float c[4],
                                         unsigned a0, unsigned a1, unsigned a2, unsigned a3,
                                         unsigned b0, unsigned b1) {
    asm volatile(
        "mma.sync.aligned.m16n8k16.row.col.f32.bf16.bf16.f32 "
        "{%0,%1,%2,%3}, {%4,%5,%6,%7}, {%8,%9}, {%0,%1,%2,%3};"
        : "+f"(c[0]), "+f"(c[1]), "+f"(c[2]), "+f"(c[3])
        : "r"(a0), "r"(a1), "r"(a2), "r"(a3), "r"(b0), "r"(b1));
}

__device__ __forceinline__ void ldsm_x2_trans(unsigned &r0, unsigned &r1, unsigned addr) {
    asm volatile("ldmatrix.sync.aligned.m8n8.x2.trans.shared.b16 {%0,%1}, [%2];"
                 : "=r"(r0), "=r"(r1) : "r"(addr));
}

__device__ __forceinline__ unsigned smem_u32(const void* p) {
    return (unsigned)__cvta_generic_to_shared(p);
}

__device__ __forceinline__ void cp_async16(unsigned dst, const void* src) {
    asm volatile("cp.async.cg.shared.global [%0], [%1], 16;" :: "r"(dst), "l"(src));
}
#define CP_COMMIT() asm volatile("cp.async.commit_group;" ::: "memory")
#define CP_WAIT0()  asm volatile("cp.async.wait_group 0;" ::: "memory")

// ======================================================================
// presplit: x fp32 -> bf16 hi/lo planes
// ======================================================================
__global__ __launch_bounds__(256)
void presplit_kernel(const float* __restrict__ x,
                     __nv_bfloat16* __restrict__ xh,
                     __nv_bfloat16* __restrict__ xl)
{
    int i = blockIdx.x * 256 + threadIdx.x;
    float2 v = ((const float2*)x)[i];
    unsigned h, l;
    split2(v.x, v.y, h, l);
    ((unsigned*)xh)[i] = h;
    ((unsigned*)xl)[i] = l;
}

// ======================================================================
// Dequant GEMM core: presplit A (cp.async) + exact-int4 B + scale fold.
// BM=128 BN=128 BK=32, 8 warps (2x4), warp tile 64x32, double-buffered.
// __launch_bounds__(256,2) on the wrappers -> 2 CTA/SM.
// ======================================================================
#define BM 128
#define BN 128
#define BK 32
#define GST 20              // padded word stride per row
#define GPL (128 * GST)     // words per plane (2560)
#define GBUF (3 * GPL)      // words per buffer (AsH | AsL | Bs)

__device__ __forceinline__ void gemm_core(
    const __nv_bfloat16* __restrict__ Ahp,
    const __nv_bfloat16* __restrict__ Alp,
    const int*   __restrict__ qw,
    const float* __restrict__ sc,
    const int*   __restrict__ qz,
    const float* __restrict__ bias,
    float* __restrict__ C,
    int N, int K, int bm, int bn, unsigned* gsm)
{
    unsigned sbase = smem_u32(gsm);

    int tid  = threadIdx.x;
    int lane = tid & 31;
    int warp = tid >> 5;
    int warp_m = warp & 1;
    int warp_n = warp >> 1;
    int t = lane & 3;
    int g = lane >> 2;

    // A cp.async mapping: 512 chunks of 16B per plane; c = tid, tid+256
    int am[2], ach[2];
#pragma unroll
    for (int i = 0; i < 2; i++) {
        int c = tid + i * 256;
        am[i]  = c >> 2;
        ach[i] = c & 3;
    }
    int n_loc = tid & 127;
    int kp0   = (tid >> 7) << 1;

    int scol[4];
#pragma unroll
    for (int ni = 0; ni < 4; ni++)
        scol[ni] = bn + warp_n * 32 + ni * 8 + (t << 1);

    float acc[4][4][4];
#pragma unroll
    for (int mi = 0; mi < 4; mi++)
#pragma unroll
        for (int ni = 0; ni < 4; ni++)
#pragma unroll
            for (int r = 0; r < 4; r++) acc[mi][ni][r] = 0.f;

    float sreg[4][2];
    unsigned bw[2];
    float bz;

    int T = K / BK;

    // ---- prologue: A tile0 via cp.async, B tile0 via regs ----
    {
        unsigned b0 = sbase;
#pragma unroll
        for (int i = 0; i < 2; i++) {
            const __nv_bfloat16* sh = Ahp + (size_t)(bm + am[i]) * K + ach[i] * 8;
            const __nv_bfloat16* sl = Alp + (size_t)(bm + am[i]) * K + ach[i] * 8;
            unsigned d = (unsigned)(am[i] * GST + ach[i] * 4) * 4;
            cp_async16(b0 + d, sh);
            cp_async16(b0 + GPL * 4 + d, sl);
        }
        CP_COMMIT();
        const int* qp = qw + (size_t)kp0 * N + bn + n_loc;
        bw[0] = (unsigned)qp[0];
        bw[1] = (unsigned)qp[N];
        bz = (float)qz[bn + n_loc];
        unsigned* Bs = gsm + 2 * GPL;
#pragma unroll
        for (int i = 0; i < 2; i++) {
            unsigned q = bw[i];
            int kpb = (kp0 + i) * 4;
#pragma unroll
            for (int j = 0; j < 4; j++)
                Bs[n_loc * GST + kpb + j] =
                    pack2((float)((q >> (8 * j)) & 15u) - bz,
                          (float)((q >> (8 * j + 4)) & 15u) - bz);
        }
        if (T > 1) {
            const int* qp1 = qw + (size_t)(4 + kp0) * N + bn + n_loc;
            bw[0] = (unsigned)qp1[0];
            bw[1] = (unsigned)qp1[N];
            bz = (float)qz[(size_t)(BK >> 7) * N + bn + n_loc];
        }
        CP_WAIT0();
        __syncthreads();
    }

    for (int it = 0; it < T; it++) {
        int k0 = it * BK;
        int b = it & 1;
        unsigned* base = gsm + b * GBUF;
        bool hasNext = (it + 1 < T);

        // ---- prefetch tile it+1 into other buffer ----
        if (hasNext) {
            int kn = k0 + BK;
            unsigned nb = sbase + ((b ^ 1) * GBUF) * 4;
#pragma unroll
            for (int i = 0; i < 2; i++) {
                const __nv_bfloat16* sh = Ahp + (size_t)(bm + am[i]) * K + kn + ach[i] * 8;
                const __nv_bfloat16* sl = Alp + (size_t)(bm + am[i]) * K + kn + ach[i] * 8;
                unsigned d = (unsigned)(am[i] * GST + ach[i] * 4) * 4;
                cp_async16(nb + d, sh);
                cp_async16(nb + GPL * 4 + d, sl);
            }
            CP_COMMIT();
            unsigned* nBs = gsm + (b ^ 1) * GBUF + 2 * GPL;
#pragma unroll
            for (int i = 0; i < 2; i++) {
                unsigned q = bw[i];
                int kpb = (kp0 + i) * 4;
#pragma unroll
                for (int j = 0; j < 4; j++)
                    nBs[n_loc * GST + kpb + j] =
                        pack2((float)((q >> (8 * j)) & 15u) - bz,
                              (float)((q >> (8 * j + 4)) & 15u) - bz);
            }
            if (it + 2 < T) {
                int kn2 = k0 + 2 * BK;
                const int* qp = qw + (size_t)((kn2 >> 3) + kp0) * N + bn + n_loc;
                bw[0] = (unsigned)qp[0];
                bw[1] = (unsigned)qp[N];
                bz = (float)qz[(size_t)(kn2 >> 7) * N + bn + n_loc];
            }
        }

        if ((k0 & 127) == 0) {
            int grp = k0 >> 7;
#pragma unroll
            for (int ni = 0; ni < 4; ni++) {
                sreg[ni][0] = sc[(size_t)grp * N + scol[ni]];
                sreg[ni][1] = sc[(size_t)grp * N + scol[ni] + 1];
            }
        }

        // ---- fragment loads ----
        const unsigned* AsH = base;
        const unsigned* AsL = base + GPL;
        const unsigned* Bs  = base + 2 * GPL;
        unsigned ah[2][4][4], al[2][4][4], bh[2][4][2];
#pragma unroll
        for (int ks = 0; ks < 2; ks++) {
            int kpb = ks * 8;
#pragma unroll
            for (int mi = 0; mi < 4; mi++) {
                int r = warp_m * 64 + mi * 16 + g;
                ah[ks][mi][0] = AsH[r * GST + kpb + t];
                ah[ks][mi][1] = AsH[(r + 8) * GST + kpb + t];
                ah[ks][mi][2] = AsH[r * GST + kpb + t + 4];
                ah[ks][mi][3] = AsH[(r + 8) * GST + kpb + t + 4];
                al[ks][mi][0] = AsL[r * GST + kpb + t];
                al[ks][mi][1] = AsL[(r + 8) * GST + kpb + t];
                al[ks][mi][2] = AsL[r * GST + kpb + t + 4];
                al[ks][mi][3] = AsL[(r + 8) * GST + kpb + t + 4];
            }
#pragma unroll
            for (int ni = 0; ni < 4; ni++) {
                int c = warp_n * 32 + ni * 8 + g;
                bh[ks][ni][0] = Bs[c * GST + kpb + t];
                bh[ks][ni][1] = Bs[c * GST + kpb + t + 4];
            }
        }

        // ---- MMA with software-pipelined scale fold ----
        float tmp[2][4];
#pragma unroll
        for (int u = 0; u < 16; u++) {
            int mi = u >> 2, ni = u & 3, pb = u & 1;
            tmp[pb][0] = 0.f; tmp[pb][1] = 0.f;
            tmp[pb][2] = 0.f; tmp[pb][3] = 0.f;
            mma_bf16(tmp[pb], ah[0][mi][0], ah[0][mi][1], ah[0][mi][2], ah[0][mi][3],
                     bh[0][ni][0], bh[0][ni][1]);
            mma_bf16(tmp[pb], al[0][mi][0], al[0][mi][1], al[0][mi][2], al[0][mi][3],
                     bh[0][ni][0], bh[0][ni][1]);
            mma_bf16(tmp[pb], ah[1][mi][0], ah[1][mi][1], ah[1][mi][2], ah[1][mi][3],
                     bh[1][ni][0], bh[1][ni][1]);
            mma_bf16(tmp[pb], al[1][mi][0], al[1][mi][1], al[1][mi][2], al[1][mi][3],
                     bh[1][ni][0], bh[1][ni][1]);
            if (u > 0) {
                int v = u - 1, vm = v >> 2, vn = v & 3, vb = v & 1;
                acc[vm][vn][0] += tmp[vb][0] * sreg[vn][0];
                acc[vm][vn][1] += tmp[vb][1] * sreg[vn][1];
                acc[vm][vn][2] += tmp[vb][2] * sreg[vn][0];
                acc[vm][vn][3] += tmp[vb][3] * sreg[vn][1];
            }
        }
        acc[3][3][0] += tmp[1][0] * sreg[3][0];
        acc[3][3][1] += tmp[1][1] * sreg[3][1];
        acc[3][3][2] += tmp[1][2] * sreg[3][0];
        acc[3][3][3] += tmp[1][3] * sreg[3][1];

        if (hasNext) CP_WAIT0();
        __syncthreads();
    }

    // ---- epilogue ----
#pragma unroll
    for (int ni = 0; ni < 4; ni++) {
        int n = scol[ni];
        float b0 = 0.f, b1 = 0.f;
        if (bias) { b0 = bias[n]; b1 = bias[n + 1]; }
#pragma unroll
        for (int mi = 0; mi < 4; mi++) {
            int m = bm + warp_m * 64 + mi * 16 + g;
            float2 v0 = make_float2(acc[mi][ni][0] + b0, acc[mi][ni][1] + b1);
            float2 v1 = make_float2(acc[mi][ni][2] + b0, acc[mi][ni][3] + b1);
            *(float2*)(C + (size_t)m * N + n) = v0;
            *(float2*)(C + (size_t)(m + 8) * N + n) = v1;
        }
    }
}

// ---- fused QKV wrapper: grid (48, 16); 2 CTAs/SM ----
__global__ __launch_bounds__(256, 2)
void gemm_qkv_kernel(const __nv_bfloat16* __restrict__ xh,
                     const __nv_bfloat16* __restrict__ xl,
    const int* __restrict__ qwq, const float* __restrict__ scq,
    const int* __restrict__ qzq, const float* __restrict__ bq,
    const int* __restrict__ qwk, const float* __restrict__ sck,
    const int* __restrict__ qzk, const float* __restrict__ bk,
    const int* __restrict__ qwv, const float* __restrict__ scv,
    const int* __restrict__ qzv, const float* __restrict__ bv,
    float* __restrict__ Cq, float* __restrict__ Ck, float* __restrict__ Cv)
{
    extern __shared__ unsigned gsm[];
    int bt = blockIdx.x;
    int bm = blockIdx.y * BM;
    const int* qw; const float* sc; const int* qz; const float* bias;
    float* C; int N; int bn;
    if (bt < 32)      { qw = qwq; sc = scq; qz = qzq; bias = bq; C = Cq; N = QDIM;  bn = bt * BN; }
    else if (bt < 40) { qw = qwk; sc = sck; qz = qzk; bias = bk; C = Ck; N = KVDIM; bn = (bt - 32) * BN; }
    else              { qw = qwv; sc = scv; qz = qzv; bias = bv; C = Cv; N = KVDIM; bn = (bt - 40) * BN; }
    gemm_core(xh, xl, qw, sc, qz, bias, C, N, HIDDEN, bm, bn, gsm);
}

__global__ __launch_bounds__(256, 2)
void gemm_o_kernel(const __nv_bfloat16* __restrict__ ah,
                   const __nv_bfloat16* __restrict__ al,
                   const int* __restrict__ qw, const float* __restrict__ sc,
                   const int* __restrict__ qz, float* __restrict__ C)
{
    extern __shared__ unsigned gsm[];
    gemm_core(ah, al, qw, sc, qz, nullptr, C, HIDDEN, QDIM,
              blockIdx.y * BM, blockIdx.x * BN, gsm);
}

// ======================================================================
// RoPE + split: Q roped in-place (fp32); K roped -> bf16 hi/lo planes;
// V -> bf16 hi/lo planes.
// ======================================================================
__global__ __launch_bounds__(256)
void rope_split_kernel(float* __restrict__ Qb,
                       const float* __restrict__ Kf,
                       const float* __restrict__ Vf,
                       __nv_bfloat16* __restrict__ Kh, __nv_bfloat16* __restrict__ Kl,
                       __nv_bfloat16* __restrict__ Vh, __nv_bfloat16* __restrict__ Vl,
                       const float* __restrict__ cosb,
                       const float* __restrict__ sinb)
{
    int s = blockIdx.y;
    int h = blockIdx.x * 4 + (threadIdx.x >> 6);
    int d = threadIdx.x & 63;

    if (h < NH) {
        float c1 = cosb[s * HD + d],     s1 = sinb[s * HD + d];
        float c2 = cosb[s * HD + d + 64], s2 = sinb[s * HD + d + 64];
        float* base = Qb + (size_t)s * QDIM + h * HD;
        float x1 = base[d], x2 = base[d + 64];
        base[d]      = x1 * c1 - x2 * s1;
        base[d + 64] = x2 * c2 + x1 * s2;
    } else if (h < NH + NKV) {
        int kh = h - NH;
        float c1 = cosb[s * HD + d],     s1 = sinb[s * HD + d];
        float c2 = cosb[s * HD + d + 64], s2 = sinb[s * HD + d + 64];
        const float* base = Kf + (size_t)s * KVDIM + kh * HD;
        float x1 = base[d], x2 = base[d + 64];
        float y1 = x1 * c1 - x2 * s1;
        float y2 = x2 * c2 + x1 * s2;
        size_t o = (size_t)s * KVDIM + kh * HD + d;
        __nv_bfloat16 h1 = __float2bfloat16(y1);
        __nv_bfloat16 h2 = __float2bfloat16(y2);
        Kh[o] = h1;       Kl[o] = __float2bfloat16(y1 - __bfloat162float(h1));
        Kh[o + 64] = h2;  Kl[o + 64] = __float2bfloat16(y2 - __bfloat162float(h2));
    } else {
        int vh = h - NH - NKV;
        const float* base = Vf + (size_t)s * KVDIM + vh * HD;
        float x1 = base[d], x2 = base[d + 64];
        size_t o = (size_t)s * KVDIM + vh * HD + d;
        __nv_bfloat16 h1 = __float2bfloat16(x1);
        __nv_bfloat16 h2 = __float2bfloat16(x2);
        Vh[o] = h1;       Vl[o] = __float2bfloat16(x1 - __bfloat162float(h1));
        Vh[o + 64] = h2;  Vl[o + 64] = __float2bfloat16(x2 - __bfloat162float(h2));
    }
}

// ======================================================================
// bf16x3 flash attention; K/V from presplit planes via cp.async.
// Output written as bf16 hi/lo planes.
// ======================================================================
#define FBQ 128
#define FBK 64
#define KVW 68
#define FPLANE (FBK * KVW)

__global__ __launch_bounds__(256, 1)
void flash_tc_kernel(const float* __restrict__ Q,
                     const __nv_bfloat16* __restrict__ Kh,
                     const __nv_bfloat16* __restrict__ Kl,
                     const __nv_bfloat16* __restrict__ Vh,
                     const __nv_bfloat16* __restrict__ Vl,
                     __nv_bfloat16* __restrict__ Oh,
                     __nv_bfloat16* __restrict__ Ol)
{
    extern __shared__ unsigned fsm[];
    unsigned (*KsH)[KVW] = (unsigned(*)[KVW])(fsm);
    unsigned (*KsL)[KVW] = (unsigned(*)[KVW])(fsm + FPLANE);
    unsigned (*VsH)[KVW] = (unsigned(*)[KVW])(fsm + 2 * FPLANE);
    unsigned (*VsL)[KVW] = (unsigned(*)[KVW])(fsm + 3 * FPLANE);

    int h = blockIdx.y;
    int qt = gridDim.x - 1 - blockIdx.x;
    int q0 = qt * FBQ;
    int kvh = h >> 2;
    int tid = threadIdx.x, lane = tid & 31, warp = tid >> 5;
    int t = lane & 3, g = lane >> 2;

    unsigned kbH = smem_u32(KsH), kbL = smem_u32(KsL);
    unsigned vbH = smem_u32(VsH), vbL = smem_u32(VsL);

    unsigned qh[8][4], ql[8][4];
    {
        const float sc = 0.08838834764831845f;
        int r0 = q0 + warp * 16 + g;
        const float* p0 = Q + (size_t)r0 * QDIM + h * HD;
        const float* p1 = p0 + 8 * QDIM;
#pragma unroll
        for (int ks = 0; ks < 8; ks++) {
            int d = ks * 16 + 2 * t;
            float2 a0 = *(const float2*)(p0 + d);
            float2 a1 = *(const float2*)(p1 + d);
            float2 a2 = *(const float2*)(p0 + d + 8);
            float2 a3 = *(const float2*)(p1 + d + 8);
            split2(a0.x * sc, a0.y * sc, qh[ks][0], ql[ks][0]);
            split2(a1.x * sc, a1.y * sc, qh[ks][1], ql[ks][1]);
            split2(a2.x * sc, a2.y * sc, qh[ks][2], ql[ks][2]);
            split2(a3.x * sc, a3.y * sc, qh[ks][3], ql[ks][3]);
        }
    }

    float m0 = -INFINITY, m1 = -INFINITY, l0s = 0.f, l1s = 0.f;
    float o_acc[16][4];
#pragma unroll
    for (int nj = 0; nj < 16; nj++)
#pragma unroll
        for (int r = 0; r < 4; r++) o_acc[nj][r] = 0.f;

    int ntiles = (q0 + FBQ) >> 6;
    for (int tt = 0; tt < ntiles; tt++) {
        int kb = tt << 6;
        __syncthreads();
#pragma unroll
        for (int i = 0; i < 4; i++) {
            int idx = tid + i * 256;
            int r = idx >> 4;
            int ch = idx & 15;
            size_t off = (size_t)(kb + r) * KVDIM + kvh * HD + ch * 8;
            unsigned d = (unsigned)(r * KVW + ch * 4) * 4;
            cp_async16(kbH + d, Kh + off);
            cp_async16(kbL + d, Kl + off);
            cp_async16(vbH + d, Vh + off);
            cp_async16(vbL + d, Vl + off);
        }
        CP_COMMIT();
        CP_WAIT0();
        __syncthreads();

        float s[8][4];
#pragma unroll
        for (int ni = 0; ni < 8; ni++)
#pragma unroll
            for (int r = 0; r < 4; r++) s[ni][r] = 0.f;

#pragma unroll
        for (int ks = 0; ks < 8; ks++) {
            int w = ks * 8 + t;
#pragma unroll
            for (int ni = 0; ni < 8; ni++) {
                int col = ni * 8 + g;
                unsigned bh0 = KsH[col][w], bh1 = KsH[col][w + 4];
                unsigned bl0 = KsL[col][w], bl1 = KsL[col][w + 4];
                mma_bf16(s[ni], qh[ks][0], qh[ks][1], qh[ks][2], qh[ks][3], bh0, bh1);
                mma_bf16(s[ni], qh[ks][0], qh[ks][1], qh[ks][2], qh[ks][3], bl0, bl1);
                mma_bf16(s[ni], ql[ks][0], ql[ks][1], ql[ks][2], ql[ks][3], bh0, bh1);
            }
        }

        if (kb + FBK > q0) {
            int r0 = q0 + warp * 16 + g, r1 = r0 + 8;
#pragma unroll
            for (int ni = 0; ni < 8; ni++) {
                int c0 = kb + ni * 8 + 2 * t, c1 = c0 + 1;
                if (c0 > r0) s[ni][0] = -INFINITY;
                if (c1 > r0) s[ni][1] = -INFINITY;
                if (c0 > r1) s[ni][2] = -INFINITY;
                if (c1 > r1) s[ni][3] = -INFINITY;
            }
        }

        float rm0 = -INFINITY, rm1 = -INFINITY;
#pragma unroll
        for (int ni = 0; ni < 8; ni++) {
            rm0 = fmaxf(rm0, fmaxf(s[ni][0], s[ni][1]));
            rm1 = fmaxf(rm1, fmaxf(s[ni][2], s[ni][3]));
        }
        rm0 = fmaxf(rm0, __shfl_xor_sync(0xffffffffu, rm0, 1));
        rm0 = fmaxf(rm0, __shfl_xor_sync(0xffffffffu, rm0, 2));
        rm1 = fmaxf(rm1, __shfl_xor_sync(0xffffffffu, rm1, 1));
        rm1 = fmaxf(rm1, __shfl_xor_sync(0xffffffffu, rm1, 2));
        float mn0 = fmaxf(m0, rm0), mn1 = fmaxf(m1, rm1);
        float cr0 = __expf(m0 - mn0), cr1 = __expf(m1 - mn1);
        m0 = mn0; m1 = mn1;
        float ps0 = 0.f, ps1 = 0.f;
#pragma unroll
        for (int ni = 0; ni < 8; ni++) {
            s[ni][0] = __expf(s[ni][0] - mn0);
            s[ni][1] = __expf(s[ni][1] - mn0);
            s[ni][2] = __expf(s[ni][2] - mn1);
            s[ni][3] = __expf(s[ni][3] - mn1);
            ps0 += s[ni][0] + s[ni][1];
            ps1 += s[ni][2] + s[ni][3];
        }
        ps0 += __shfl_xor_sync(0xffffffffu, ps0, 1);
        ps0 += __shfl_xor_sync(0xffffffffu, ps0, 2);
        ps1 += __shfl_xor_sync(0xffffffffu, ps1, 1);
        ps1 += __shfl_xor_sync(0xffffffffu, ps1, 2);
        l0s = l0s * cr0 + ps0;
        l1s = l1s * cr1 + ps1;
#pragma unroll
        for (int nj = 0; nj < 16; nj++) {
            o_acc[nj][0] *= cr0; o_acc[nj][1] *= cr0;
            o_acc[nj][2] *= cr1; o_acc[nj][3] *= cr1;
        }

#pragma unroll
        for (int ks2 = 0; ks2 < 4; ks2++) {
            unsigned ph[4], pl[4];
            split2(s[2 * ks2][0],     s[2 * ks2][1],     ph[0], pl[0]);
            split2(s[2 * ks2][2],     s[2 * ks2][3],     ph[1], pl[1]);
            split2(s[2 * ks2 + 1][0], s[2 * ks2 + 1][1], ph[2], pl[2]);
            split2(s[2 * ks2 + 1][2], s[2 * ks2 + 1][3], ph[3], pl[3]);
            unsigned rowb = (unsigned)(ks2 * 16 + (lane & 15)) * (KVW * 4);
#pragma unroll
            for (int nj = 0; nj < 16; nj++) {
                unsigned v0, v1, u0, u1;
                ldsm_x2_trans(v0, v1, vbH + rowb + nj * 16);
                ldsm_x2_trans(u0, u1, vbL + rowb + nj * 16);
                mma_bf16(o_acc[nj], ph[0], ph[1], ph[2], ph[3], v0, v1);
                mma_bf16(o_acc[nj], ph[0], ph[1], ph[2], ph[3], u0, u1);
                mma_bf16(o_acc[nj], pl[0], pl[1], pl[2], pl[3], v0, v1);
            }
        }
    }

    float inv0 = 1.f / l0s, inv1 = 1.f / l1s;
    int r0 = q0 + warp * 16 + g;
    size_t b0 = (size_t)r0 * QDIM + h * HD;
    size_t b1 = b0 + 8 * (size_t)QDIM;
#pragma unroll
    for (int nj = 0; nj < 16; nj++) {
        int d = nj * 8 + 2 * t;
        unsigned hh, ll;
        split2(o_acc[nj][0] * inv0, o_acc[nj][1] * inv0, hh, ll);
        *(unsigned*)(Oh + b0 + d) = hh;
        *(unsigned*)(Ol + b0 + d) = ll;
        split2(o_acc[nj][2] * inv1, o_acc[nj][3] * inv1, hh, ll);
        *(unsigned*)(Oh + b1 + d) = hh;
        *(unsigned*)(Ol + b1 + d) = ll;
    }
}

// ======================================================================
// Launch
// ======================================================================
extern "C" void kernel_launch(void* const* d_in, const int* in_sizes, int n_in,
                              void* d_out, int out_size)
{
    const float* x        = (const float*)d_in[0];
    const float* cosb     = (const float*)d_in[1];
    const float* sinb     = (const float*)d_in[2];
    const float* q_scales = (const float*)d_in[3];
    const float* q_bias   = (const float*)d_in[4];
    const float* k_scales = (const float*)d_in[5];
    const float* k_bias   = (const float*)d_in[6];
    const float* v_scales = (const float*)d_in[7];
    const float* v_bias   = (const float*)d_in[8];
    const float* o_scales = (const float*)d_in[9];
    const int* q_qweight  = (const int*)d_in[10];
    const int* q_qzeros   = (const int*)d_in[11];
    const int* k_qweight  = (const int*)d_in[12];
    const int* k_qzeros   = (const int*)d_in[13];
    const int* v_qweight  = (const int*)d_in[14];
    const int* v_qzeros   = (const int*)d_in[15];
    const int* o_qweight  = (const int*)d_in[16];
    const int* o_qzeros   = (const int*)d_in[17];
    float* out = (float*)d_out;

    float *pq, *pk, *pv;
    __nv_bfloat16 *pxh, *pxl, *pkh, *pkl, *pvh, *pvl, *pah, *pal;
    cudaGetSymbolAddress((void**)&pq, g_q);
    cudaGetSymbolAddress((void**)&pk, g_k);
    cudaGetSymbolAddress((void**)&pv, g_v);
    cudaGetSymbolAddress((void**)&pxh, g_xh);
    cudaGetSymbolAddress((void**)&pxl, g_xl);
    cudaGetSymbolAddress((void**)&pkh, g_kh);
    cudaGetSymbolAddress((void**)&pkl, g_kl);
    cudaGetSymbolAddress((void**)&pvh, g_vh);
    cudaGetSymbolAddress((void**)&pvl, g_vl);
    cudaGetSymbolAddress((void**)&pah, g_ah);
    cudaGetSymbolAddress((void**)&pal, g_al);

    size_t gsmem = (size_t)(2 * GBUF) * sizeof(unsigned);   // 61440 B
    cudaFuncSetAttribute(gemm_qkv_kernel,
                         cudaFuncAttributeMaxDynamicSharedMemorySize, (int)gsmem);
    cudaFuncSetAttribute(gemm_o_kernel,
                         cudaFuncAttributeMaxDynamicSharedMemorySize, (int)gsmem);

    // presplit x
    presplit_kernel<<<(S_LEN * HIDDEN / 2) / 256, 256>>>(x, pxh, pxl);

    // fused QKV projection
    {
        dim3 grid(48, S_LEN / BM);
        gemm_qkv_kernel<<<grid, 256, gsmem>>>(
            pxh, pxl,
            q_qweight, q_scales, q_qzeros, q_bias,
            k_qweight, k_scales, k_qzeros, k_bias,
            v_qweight, v_scales, v_qzeros, v_bias,
            pq, pk, pv);
    }

    // RoPE (Q in-place) + K/V presplit
    {
        dim3 grid(12, S_LEN);
        rope_split_kernel<<<grid, 256>>>(pq, pk, pv, pkh, pkl, pvh, pvl, cosb, sinb);
    }

    // Flash attention
    {
        size_t smem = (size_t)(4 * FPLANE) * sizeof(unsigned);
        cudaFuncSetAttribute(flash_tc_kernel,
                             cudaFuncAttributeMaxDynamicSharedMemorySize, (int)smem);
        dim3 grid(S_LEN / FBQ, NH);
        flash_tc_kernel<<<grid, 256, smem>>>(pq, pkh, pkl, pvh, pvl, pah, pal);
    }

    // O projection
    {
        dim3 grid(HIDDEN / BN, S_LEN / BM);
        gemm_o_kernel<<<grid, 256, gsmem>>>(pah, pal, o_qweight, o_scales, o_qzeros, out);
    }
}

// round 9
// speedup vs baseline: 3.8148x; 1.0143x over previous
#include <cuda_runtime.h>
#include <cuda_bf16.h>
#include <math.h>

// Problem constants
#define S_LEN 2048
#define HIDDEN 2560
#define NH 32
#define NKV 8
#define HD 128
#define QDIM (NH*HD)    // 4096
#define KVDIM (NKV*HD)  // 1024
#define GS 128

// -------- scratch (static device arrays; no allocation allowed) --------
__device__ float g_q[S_LEN * QDIM];            // Q fp32 (roped in-place)
__device__ float g_k[S_LEN * KVDIM];           // K fp32 (pre-rope)
__device__ float g_v[S_LEN * KVDIM];           // V fp32
__device__ __nv_bfloat16 g_xh[S_LEN * HIDDEN], g_xl[S_LEN * HIDDEN];
__device__ __nv_bfloat16 g_kh[S_LEN * KVDIM], g_kl[S_LEN * KVDIM];
__device__ __nv_bfloat16 g_vh[S_LEN * KVDIM], g_vl[S_LEN * KVDIM];
__device__ __nv_bfloat16 g_ah[S_LEN * QDIM],  g_al[S_LEN * QDIM];

// ======================================================================
// helpers
// ======================================================================
__device__ __forceinline__ void split2(float f0, float f1,
                                       unsigned &hi, unsigned &lo) {
    __nv_bfloat16 h0 = __float2bfloat16(f0);
    __nv_bfloat16 h1 = __float2bfloat16(f1);
    __nv_bfloat16 l0 = __float2bfloat16(f0 - __bfloat162float(h0));
    __nv_bfloat16 l1 = __float2bfloat16(f1 - __bfloat162float(h1));
    hi = (unsigned)__bfloat16_as_ushort(h0) |
         ((unsigned)__bfloat16_as_ushort(h1) << 16);
    lo = (unsigned)__bfloat16_as_ushort(l0) |
         ((unsigned)__bfloat16_as_ushort(l1) << 16);
}

__device__ __forceinline__ unsigned pack2(float f0, float f1) {
    return (unsigned)__bfloat16_as_ushort(__float2bfloat16(f0)) |
           ((unsigned)__bfloat16_as_ushort(__float2bfloat16(f1)) << 16);
}

__device__ __forceinline__ void mma_bf16(float c[4],
                                         unsigned a0, unsigned a1, unsigned a2, unsigned a3,
                                         unsigned b0, unsigned b1) {
    asm volatile(
        "mma.sync.aligned.m16n8k16.row.col.f32.bf16.bf16.f32 "
        "{%0,%1,%2,%3}, {%4,%5,%6,%7}, {%8,%9}, {%0,%1,%2,%3};"
        : "+f"(c[0]), "+f"(c[1]), "+f"(c[2]), "+f"(c[3])
        : "r"(a0), "r"(a1), "r"(a2), "r"(a3), "r"(b0), "r"(b1));
}

__device__ __forceinline__ void ldsm_x2_trans(unsigned &r0, unsigned &r1, unsigned addr) {
    asm volatile("ldmatrix.sync.aligned.m8n8.x2.trans.shared.b16 {%0,%1}, [%2];"
                 : "=r"(r0), "=r"(r1) : "r"(addr));
}

__device__ __forceinline__ unsigned smem_u32(const void* p) {
    return (unsigned)__cvta_generic_to_shared(p);
}

__device__ __forceinline__ void cp_async16(unsigned dst, const void* src) {
    asm volatile("cp.async.cg.shared.global [%0], [%1], 16;" :: "r"(dst), "l"(src));
}
#define CP_COMMIT() asm volatile("cp.async.commit_group;" ::: "memory")
#define CP_WAIT0()  asm volatile("cp.async.wait_group 0;" ::: "memory")

// ======================================================================
// presplit: x fp32 -> bf16 hi/lo planes
// ======================================================================
__global__ __launch_bounds__(256)
void presplit_kernel(const float* __restrict__ x,
                     __nv_bfloat16* __restrict__ xh,
                     __nv_bfloat16* __restrict__ xl)
{
    int i = blockIdx.x * 256 + threadIdx.x;
    float2 v = ((const float2*)x)[i];
    unsigned h, l;
    split2(v.x, v.y, h, l);
    ((unsigned*)xh)[i] = h;
    ((unsigned*)xl)[i] = l;
}

// ======================================================================
// Dequant GEMM core (validated R8): presplit A + exact-int4 B + scale fold
// ======================================================================
#define BM 128
#define BN 128
#define BK 32
#define GST 20
#define GPL (128 * GST)
#define GBUF (3 * GPL)

__device__ __forceinline__ void gemm_core(
    const __nv_bfloat16* __restrict__ Ahp,
    const __nv_bfloat16* __restrict__ Alp,
    const int*   __restrict__ qw,
    const float* __restrict__ sc,
    const int*   __restrict__ qz,
    const float* __restrict__ bias,
    float* __restrict__ C,
    int N, int K, int bm, int bn, unsigned* gsm)
{
    unsigned sbase = smem_u32(gsm);

    int tid  = threadIdx.x;
    int lane = tid & 31;
    int warp = tid >> 5;
    int warp_m = warp & 1;
    int warp_n = warp >> 1;
    int t = lane & 3;
    int g = lane >> 2;

    int am[2], ach[2];
#pragma unroll
    for (int i = 0; i < 2; i++) {
        int c = tid + i * 256;
        am[i]  = c >> 2;
        ach[i] = c & 3;
    }
    int n_loc = tid & 127;
    int kp0   = (tid >> 7) << 1;

    int scol[4];
#pragma unroll
    for (int ni = 0; ni < 4; ni++)
        scol[ni] = bn + warp_n * 32 + ni * 8 + (t << 1);

    float acc[4][4][4];
#pragma unroll
    for (int mi = 0; mi < 4; mi++)
#pragma unroll
        for (int ni = 0; ni < 4; ni++)
#pragma unroll
            for (int r = 0; r < 4; r++) acc[mi][ni][r] = 0.f;

    float sreg[4][2];
    unsigned bw[2];
    float bz;

    int T = K / BK;

    {
        unsigned b0 = sbase;
#pragma unroll
        for (int i = 0; i < 2; i++) {
            const __nv_bfloat16* sh = Ahp + (size_t)(bm + am[i]) * K + ach[i] * 8;
            const __nv_bfloat16* sl = Alp + (size_t)(bm + am[i]) * K + ach[i] * 8;
            unsigned d = (unsigned)(am[i] * GST + ach[i] * 4) * 4;
            cp_async16(b0 + d, sh);
            cp_async16(b0 + GPL * 4 + d, sl);
        }
        CP_COMMIT();
        const int* qp = qw + (size_t)kp0 * N + bn + n_loc;
        bw[0] = (unsigned)qp[0];
        bw[1] = (unsigned)qp[N];
        bz = (float)qz[bn + n_loc];
        unsigned* Bs = gsm + 2 * GPL;
#pragma unroll
        for (int i = 0; i < 2; i++) {
            unsigned q = bw[i];
            int kpb = (kp0 + i) * 4;
#pragma unroll
            for (int j = 0; j < 4; j++)
                Bs[n_loc * GST + kpb + j] =
                    pack2((float)((q >> (8 * j)) & 15u) - bz,
                          (float)((q >> (8 * j + 4)) & 15u) - bz);
        }
        if (T > 1) {
            const int* qp1 = qw + (size_t)(4 + kp0) * N + bn + n_loc;
            bw[0] = (unsigned)qp1[0];
            bw[1] = (unsigned)qp1[N];
            bz = (float)qz[(size_t)(BK >> 7) * N + bn + n_loc];
        }
        CP_WAIT0();
        __syncthreads();
    }

    for (int it = 0; it < T; it++) {
        int k0 = it * BK;
        int b = it & 1;
        unsigned* base = gsm + b * GBUF;
        bool hasNext = (it + 1 < T);

        if (hasNext) {
            int kn = k0 + BK;
            unsigned nb = sbase + ((b ^ 1) * GBUF) * 4;
#pragma unroll
            for (int i = 0; i < 2; i++) {
                const __nv_bfloat16* sh = Ahp + (size_t)(bm + am[i]) * K + kn + ach[i] * 8;
                const __nv_bfloat16* sl = Alp + (size_t)(bm + am[i]) * K + kn + ach[i] * 8;
                unsigned d = (unsigned)(am[i] * GST + ach[i] * 4) * 4;
                cp_async16(nb + d, sh);
                cp_async16(nb + GPL * 4 + d, sl);
            }
            CP_COMMIT();
            unsigned* nBs = gsm + (b ^ 1) * GBUF + 2 * GPL;
#pragma unroll
            for (int i = 0; i < 2; i++) {
                unsigned q = bw[i];
                int kpb = (kp0 + i) * 4;
#pragma unroll
                for (int j = 0; j < 4; j++)
                    nBs[n_loc * GST + kpb + j] =
                        pack2((float)((q >> (8 * j)) & 15u) - bz,
                              (float)((q >> (8 * j + 4)) & 15u) - bz);
            }
            if (it + 2 < T) {
                int kn2 = k0 + 2 * BK;
                const int* qp = qw + (size_t)((kn2 >> 3) + kp0) * N + bn + n_loc;
                bw[0] = (unsigned)qp[0];
                bw[1] = (unsigned)qp[N];
                bz = (float)qz[(size_t)(kn2 >> 7) * N + bn + n_loc];
            }
        }

        if ((k0 & 127) == 0) {
            int grp = k0 >> 7;
#pragma unroll
            for (int ni = 0; ni < 4; ni++) {
                sreg[ni][0] = sc[(size_t)grp * N + scol[ni]];
                sreg[ni][1] = sc[(size_t)grp * N + scol[ni] + 1];
            }
        }

        const unsigned* AsH = base;
        const unsigned* AsL = base + GPL;
        const unsigned* Bs  = base + 2 * GPL;
        unsigned ah[2][4][4], al[2][4][4], bh[2][4][2];
#pragma unroll
        for (int ks = 0; ks < 2; ks++) {
            int kpb = ks * 8;
#pragma unroll
            for (int mi = 0; mi < 4; mi++) {
                int r = warp_m * 64 + mi * 16 + g;
                ah[ks][mi][0] = AsH[r * GST + kpb + t];
                ah[ks][mi][1] = AsH[(r + 8) * GST + kpb + t];
                ah[ks][mi][2] = AsH[r * GST + kpb + t + 4];
                ah[ks][mi][3] = AsH[(r + 8) * GST + kpb + t + 4];
                al[ks][mi][0] = AsL[r * GST + kpb + t];
                al[ks][mi][1] = AsL[(r + 8) * GST + kpb + t];
                al[ks][mi][2] = AsL[r * GST + kpb + t + 4];
                al[ks][mi][3] = AsL[(r + 8) * GST + kpb + t + 4];
            }
#pragma unroll
            for (int ni = 0; ni < 4; ni++) {
                int c = warp_n * 32 + ni * 8 + g;
                bh[ks][ni][0] = Bs[c * GST + kpb + t];
                bh[ks][ni][1] = Bs[c * GST + kpb + t + 4];
            }
        }

        float tmp[2][4];
#pragma unroll
        for (int u = 0; u < 16; u++) {
            int mi = u >> 2, ni = u & 3, pb = u & 1;
            tmp[pb][0] = 0.f; tmp[pb][1] = 0.f;
            tmp[pb][2] = 0.f; tmp[pb][3] = 0.f;
            mma_bf16(tmp[pb], ah[0][mi][0], ah[0][mi][1], ah[0][mi][2], ah[0][mi][3],
                     bh[0][ni][0], bh[0][ni][1]);
            mma_bf16(tmp[pb], al[0][mi][0], al[0][mi][1], al[0][mi][2], al[0][mi][3],
                     bh[0][ni][0], bh[0][ni][1]);
            mma_bf16(tmp[pb], ah[1][mi][0], ah[1][mi][1], ah[1][mi][2], ah[1][mi][3],
                     bh[1][ni][0], bh[1][ni][1]);
            mma_bf16(tmp[pb], al[1][mi][0], al[1][mi][1], al[1][mi][2], al[1][mi][3],
                     bh[1][ni][0], bh[1][ni][1]);
            if (u > 0) {
                int v = u - 1, vm = v >> 2, vn = v & 3, vb = v & 1;
                acc[vm][vn][0] += tmp[vb][0] * sreg[vn][0];
                acc[vm][vn][1] += tmp[vb][1] * sreg[vn][1];
                acc[vm][vn][2] += tmp[vb][2] * sreg[vn][0];
                acc[vm][vn][3] += tmp[vb][3] * sreg[vn][1];
            }
        }
        acc[3][3][0] += tmp[1][0] * sreg[3][0];
        acc[3][3][1] += tmp[1][1] * sreg[3][1];
        acc[3][3][2] += tmp[1][2] * sreg[3][0];
        acc[3][3][3] += tmp[1][3] * sreg[3][1];

        if (hasNext) CP_WAIT0();
        __syncthreads();
    }

#pragma unroll
    for (int ni = 0; ni < 4; ni++) {
        int n = scol[ni];
        float b0 = 0.f, b1 = 0.f;
        if (bias) { b0 = bias[n]; b1 = bias[n + 1]; }
#pragma unroll
        for (int mi = 0; mi < 4; mi++) {
            int m = bm + warp_m * 64 + mi * 16 + g;
            float2 v0 = make_float2(acc[mi][ni][0] + b0, acc[mi][ni][1] + b1);
            float2 v1 = make_float2(acc[mi][ni][2] + b0, acc[mi][ni][3] + b1);
            *(float2*)(C + (size_t)m * N + n) = v0;
            *(float2*)(C + (size_t)(m + 8) * N + n) = v1;
        }
    }
}

__global__ __launch_bounds__(256, 2)
void gemm_qkv_kernel(const __nv_bfloat16* __restrict__ xh,
                     const __nv_bfloat16* __restrict__ xl,
    const int* __restrict__ qwq, const float* __restrict__ scq,
    const int* __restrict__ qzq, const float* __restrict__ bq,
    const int* __restrict__ qwk, const float* __restrict__ sck,
    const int* __restrict__ qzk, const float* __restrict__ bk,
    const int* __restrict__ qwv, const float* __restrict__ scv,
    const int* __restrict__ qzv, const float* __restrict__ bv,
    float* __restrict__ Cq, float* __restrict__ Ck, float* __restrict__ Cv)
{
    extern __shared__ unsigned gsm[];
    int bt = blockIdx.x;
    int bm = blockIdx.y * BM;
    const int* qw; const float* sc; const int* qz; const float* bias;
    float* C; int N; int bn;
    if (bt < 32)      { qw = qwq; sc = scq; qz = qzq; bias = bq; C = Cq; N = QDIM;  bn = bt * BN; }
    else if (bt < 40) { qw = qwk; sc = sck; qz = qzk; bias = bk; C = Ck; N = KVDIM; bn = (bt - 32) * BN; }
    else              { qw = qwv; sc = scv; qz = qzv; bias = bv; C = Cv; N = KVDIM; bn = (bt - 40) * BN; }
    gemm_core(xh, xl, qw, sc, qz, bias, C, N, HIDDEN, bm, bn, gsm);
}

__global__ __launch_bounds__(256, 2)
void gemm_o_kernel(const __nv_bfloat16* __restrict__ ah,
                   const __nv_bfloat16* __restrict__ al,
                   const int* __restrict__ qw, const float* __restrict__ sc,
                   const int* __restrict__ qz, float* __restrict__ C)
{
    extern __shared__ unsigned gsm[];
    gemm_core(ah, al, qw, sc, qz, nullptr, C, HIDDEN, QDIM,
              blockIdx.y * BM, blockIdx.x * BN, gsm);
}

// ======================================================================
// RoPE + split (unchanged)
// ======================================================================
__global__ __launch_bounds__(256)
void rope_split_kernel(float* __restrict__ Qb,
                       const float* __restrict__ Kf,
                       const float* __restrict__ Vf,
                       __nv_bfloat16* __restrict__ Kh, __nv_bfloat16* __restrict__ Kl,
                       __nv_bfloat16* __restrict__ Vh, __nv_bfloat16* __restrict__ Vl,
                       const float* __restrict__ cosb,
                       const float* __restrict__ sinb)
{
    int s = blockIdx.y;
    int h = blockIdx.x * 4 + (threadIdx.x >> 6);
    int d = threadIdx.x & 63;

    if (h < NH) {
        float c1 = cosb[s * HD + d],     s1 = sinb[s * HD + d];
        float c2 = cosb[s * HD + d + 64], s2 = sinb[s * HD + d + 64];
        float* base = Qb + (size_t)s * QDIM + h * HD;
        float x1 = base[d], x2 = base[d + 64];
        base[d]      = x1 * c1 - x2 * s1;
        base[d + 64] = x2 * c2 + x1 * s2;
    } else if (h < NH + NKV) {
        int kh = h - NH;
        float c1 = cosb[s * HD + d],     s1 = sinb[s * HD + d];
        float c2 = cosb[s * HD + d + 64], s2 = sinb[s * HD + d + 64];
        const float* base = Kf + (size_t)s * KVDIM + kh * HD;
        float x1 = base[d], x2 = base[d + 64];
        float y1 = x1 * c1 - x2 * s1;
        float y2 = x2 * c2 + x1 * s2;
        size_t o = (size_t)s * KVDIM + kh * HD + d;
        __nv_bfloat16 h1 = __float2bfloat16(y1);
        __nv_bfloat16 h2 = __float2bfloat16(y2);
        Kh[o] = h1;       Kl[o] = __float2bfloat16(y1 - __bfloat162float(h1));
        Kh[o + 64] = h2;  Kl[o + 64] = __float2bfloat16(y2 - __bfloat162float(h2));
    } else {
        int vh = h - NH - NKV;
        const float* base = Vf + (size_t)s * KVDIM + vh * HD;
        float x1 = base[d], x2 = base[d + 64];
        size_t o = (size_t)s * KVDIM + vh * HD + d;
        __nv_bfloat16 h1 = __float2bfloat16(x1);
        __nv_bfloat16 h2 = __float2bfloat16(x2);
        Vh[o] = h1;       Vl[o] = __float2bfloat16(x1 - __bfloat162float(h1));
        Vh[o + 64] = h2;  Vl[o + 64] = __float2bfloat16(x2 - __bfloat162float(h2));
    }
}

// ======================================================================
// bf16x3 flash attention: FBQ=64, 128-thread CTAs, 2 CTAs/SM.
// ======================================================================
#define FBQ 64
#define FBK 64
#define FTHREADS 128
#define KVW 68
#define FPLANE (FBK * KVW)

__global__ __launch_bounds__(FTHREADS, 2)
void flash_tc_kernel(const float* __restrict__ Q,
                     const __nv_bfloat16* __restrict__ Kh,
                     const __nv_bfloat16* __restrict__ Kl,
                     const __nv_bfloat16* __restrict__ Vh,
                     const __nv_bfloat16* __restrict__ Vl,
                     __nv_bfloat16* __restrict__ Oh,
                     __nv_bfloat16* __restrict__ Ol)
{
    extern __shared__ unsigned fsm[];
    unsigned (*KsH)[KVW] = (unsigned(*)[KVW])(fsm);
    unsigned (*KsL)[KVW] = (unsigned(*)[KVW])(fsm + FPLANE);
    unsigned (*VsH)[KVW] = (unsigned(*)[KVW])(fsm + 2 * FPLANE);
    unsigned (*VsL)[KVW] = (unsigned(*)[KVW])(fsm + 3 * FPLANE);

    int h = blockIdx.y;
    int qt = gridDim.x - 1 - blockIdx.x;   // largest q-tile first
    int q0 = qt * FBQ;
    int kvh = h >> 2;
    int tid = threadIdx.x, lane = tid & 31, warp = tid >> 5;   // warp 0..3
    int t = lane & 3, g = lane >> 2;

    unsigned kbH = smem_u32(KsH), kbL = smem_u32(KsL);
    unsigned vbH = smem_u32(VsH), vbL = smem_u32(VsL);

    // ---- Q fragments, scale folded, split hi/lo (regs) ----
    unsigned qh[8][4], ql[8][4];
    {
        const float sc = 0.08838834764831845f;
        int r0 = q0 + warp * 16 + g;
        const float* p0 = Q + (size_t)r0 * QDIM + h * HD;
        const float* p1 = p0 + 8 * QDIM;
#pragma unroll
        for (int ks = 0; ks < 8; ks++) {
            int d = ks * 16 + 2 * t;
            float2 a0 = *(const float2*)(p0 + d);
            float2 a1 = *(const float2*)(p1 + d);
            float2 a2 = *(const float2*)(p0 + d + 8);
            float2 a3 = *(const float2*)(p1 + d + 8);
            split2(a0.x * sc, a0.y * sc, qh[ks][0], ql[ks][0]);
            split2(a1.x * sc, a1.y * sc, qh[ks][1], ql[ks][1]);
            split2(a2.x * sc, a2.y * sc, qh[ks][2], ql[ks][2]);
            split2(a3.x * sc, a3.y * sc, qh[ks][3], ql[ks][3]);
        }
    }

    float m0 = -INFINITY, m1 = -INFINITY, l0s = 0.f, l1s = 0.f;
    float o_acc[16][4];
#pragma unroll
    for (int nj = 0; nj < 16; nj++)
#pragma unroll
        for (int r = 0; r < 4; r++) o_acc[nj][r] = 0.f;

    int ntiles = qt + 1;
    for (int tt = 0; tt < ntiles; tt++) {
        int kb = tt << 6;
        __syncthreads();
        // ---- cp.async K/V tiles (1024 chunks/plane; 8 per thread) ----
#pragma unroll
        for (int i = 0; i < 8; i++) {
            int idx = tid + i * FTHREADS;
            int r = idx >> 4;
            int ch = idx & 15;
            size_t off = (size_t)(kb + r) * KVDIM + kvh * HD + ch * 8;
            unsigned d = (unsigned)(r * KVW + ch * 4) * 4;
            cp_async16(kbH + d, Kh + off);
            cp_async16(kbL + d, Kl + off);
            cp_async16(vbH + d, Vh + off);
            cp_async16(vbL + d, Vl + off);
        }
        CP_COMMIT();
        CP_WAIT0();
        __syncthreads();

        // ---- scores S = Q K^T (bf16x3) ----
        float s[8][4];
#pragma unroll
        for (int ni = 0; ni < 8; ni++)
#pragma unroll
            for (int r = 0; r < 4; r++) s[ni][r] = 0.f;

#pragma unroll
        for (int ks = 0; ks < 8; ks++) {
            int w = ks * 8 + t;
#pragma unroll
            for (int ni = 0; ni < 8; ni++) {
                int col = ni * 8 + g;
                unsigned bh0 = KsH[col][w], bh1 = KsH[col][w + 4];
                unsigned bl0 = KsL[col][w], bl1 = KsL[col][w + 4];
                mma_bf16(s[ni], qh[ks][0], qh[ks][1], qh[ks][2], qh[ks][3], bh0, bh1);
                mma_bf16(s[ni], qh[ks][0], qh[ks][1], qh[ks][2], qh[ks][3], bl0, bl1);
                mma_bf16(s[ni], ql[ks][0], ql[ks][1], ql[ks][2], ql[ks][3], bh0, bh1);
            }
        }

        // ---- causal mask (diagonal tile only) ----
        if (kb + FBK > q0) {
            int r0 = q0 + warp * 16 + g, r1 = r0 + 8;
#pragma unroll
            for (int ni = 0; ni < 8; ni++) {
                int c0 = kb + ni * 8 + 2 * t, c1 = c0 + 1;
                if (c0 > r0) s[ni][0] = -INFINITY;
                if (c1 > r0) s[ni][1] = -INFINITY;
                if (c0 > r1) s[ni][2] = -INFINITY;
                if (c1 > r1) s[ni][3] = -INFINITY;
            }
        }

        // ---- online softmax ----
        float rm0 = -INFINITY, rm1 = -INFINITY;
#pragma unroll
        for (int ni = 0; ni < 8; ni++) {
            rm0 = fmaxf(rm0, fmaxf(s[ni][0], s[ni][1]));
            rm1 = fmaxf(rm1, fmaxf(s[ni][2], s[ni][3]));
        }
        rm0 = fmaxf(rm0, __shfl_xor_sync(0xffffffffu, rm0, 1));
        rm0 = fmaxf(rm0, __shfl_xor_sync(0xffffffffu, rm0, 2));
        rm1 = fmaxf(rm1, __shfl_xor_sync(0xffffffffu, rm1, 1));
        rm1 = fmaxf(rm1, __shfl_xor_sync(0xffffffffu, rm1, 2));
        float mn0 = fmaxf(m0, rm0), mn1 = fmaxf(m1, rm1);
        float cr0 = __expf(m0 - mn0), cr1 = __expf(m1 - mn1);
        m0 = mn0; m1 = mn1;
        float ps0 = 0.f, ps1 = 0.f;
#pragma unroll
        for (int ni = 0; ni < 8; ni++) {
            s[ni][0] = __expf(s[ni][0] - mn0);
            s[ni][1] = __expf(s[ni][1] - mn0);
            s[ni][2] = __expf(s[ni][2] - mn1);
            s[ni][3] = __expf(s[ni][3] - mn1);
            ps0 += s[ni][0] + s[ni][1];
            ps1 += s[ni][2] + s[ni][3];
        }
        ps0 += __shfl_xor_sync(0xffffffffu, ps0, 1);
        ps0 += __shfl_xor_sync(0xffffffffu, ps0, 2);
        ps1 += __shfl_xor_sync(0xffffffffu, ps1, 1);
        ps1 += __shfl_xor_sync(0xffffffffu, ps1, 2);
        l0s = l0s * cr0 + ps0;
        l1s = l1s * cr1 + ps1;
#pragma unroll
        for (int nj = 0; nj < 16; nj++) {
            o_acc[nj][0] *= cr0; o_acc[nj][1] *= cr0;
            o_acc[nj][2] *= cr1; o_acc[nj][3] *= cr1;
        }

        // ---- O += P V (bf16x3) ----
#pragma unroll
        for (int ks2 = 0; ks2 < 4; ks2++) {
            unsigned ph[4], pl[4];
            split2(s[2 * ks2][0],     s[2 * ks2][1],     ph[0], pl[0]);
            split2(s[2 * ks2][2],     s[2 * ks2][3],     ph[1], pl[1]);
            split2(s[2 * ks2 + 1][0], s[2 * ks2 + 1][1], ph[2], pl[2]);
            split2(s[2 * ks2 + 1][2], s[2 * ks2 + 1][3], ph[3], pl[3]);
            unsigned rowb = (unsigned)(ks2 * 16 + (lane & 15)) * (KVW * 4);
#pragma unroll
            for (int nj = 0; nj < 16; nj++) {
                unsigned v0, v1, u0, u1;
                ldsm_x2_trans(v0, v1, vbH + rowb + nj * 16);
                ldsm_x2_trans(u0, u1, vbL + rowb + nj * 16);
                mma_bf16(o_acc[nj], ph[0], ph[1], ph[2], ph[3], v0, v1);
                mma_bf16(o_acc[nj], ph[0], ph[1], ph[2], ph[3], u0, u1);
                mma_bf16(o_acc[nj], pl[0], pl[1], pl[2], pl[3], v0, v1);
            }
        }
    }

    // ---- epilogue: write bf16 hi/lo planes ----
    float inv0 = 1.f / l0s, inv1 = 1.f / l1s;
    int r0 = q0 + warp * 16 + g;
    size_t b0 = (size_t)r0 * QDIM + h * HD;
    size_t b1 = b0 + 8 * (size_t)QDIM;
#pragma unroll
    for (int nj = 0; nj < 16; nj++) {
        int d = nj * 8 + 2 * t;
        unsigned hh, ll;
        split2(o_acc[nj][0] * inv0, o_acc[nj][1] * inv0, hh, ll);
        *(unsigned*)(Oh + b0 + d) = hh;
        *(unsigned*)(Ol + b0 + d) = ll;
        split2(o_acc[nj][2] * inv1, o_acc[nj][3] * inv1, hh, ll);
        *(unsigned*)(Oh + b1 + d) = hh;
        *(unsigned*)(Ol + b1 + d) = ll;
    }
}

// ======================================================================
// Launch
// ======================================================================
extern "C" void kernel_launch(void* const* d_in, const int* in_sizes, int n_in,
                              void* d_out, int out_size)
{
    const float* x        = (const float*)d_in[0];
    const float* cosb     = (const float*)d_in[1];
    const float* sinb     = (const float*)d_in[2];
    const float* q_scales = (const float*)d_in[3];
    const float* q_bias   = (const float*)d_in[4];
    const float* k_scales = (const float*)d_in[5];
    const float* k_bias   = (const float*)d_in[6];
    const float* v_scales = (const float*)d_in[7];
    const float* v_bias   = (const float*)d_in[8];
    const float* o_scales = (const float*)d_in[9];
    const int* q_qweight  = (const int*)d_in[10];
    const int* q_qzeros   = (const int*)d_in[11];
    const int* k_qweight  = (const int*)d_in[12];
    const int* k_qzeros   = (const int*)d_in[13];
    const int* v_qweight  = (const int*)d_in[14];
    const int* v_qzeros   = (const int*)d_in[15];
    const int* o_qweight  = (const int*)d_in[16];
    const int* o_qzeros   = (const int*)d_in[17];
    float* out = (float*)d_out;

    float *pq, *pk, *pv;
    __nv_bfloat16 *pxh, *pxl, *pkh, *pkl, *pvh, *pvl, *pah, *pal;
    cudaGetSymbolAddress((void**)&pq, g_q);
    cudaGetSymbolAddress((void**)&pk, g_k);
    cudaGetSymbolAddress((void**)&pv, g_v);
    cudaGetSymbolAddress((void**)&pxh, g_xh);
    cudaGetSymbolAddress((void**)&pxl, g_xl);
    cudaGetSymbolAddress((void**)&pkh, g_kh);
    cudaGetSymbolAddress((void**)&pkl, g_kl);
    cudaGetSymbolAddress((void**)&pvh, g_vh);
    cudaGetSymbolAddress((void**)&pvl, g_vl);
    cudaGetSymbolAddress((void**)&pah, g_ah);
    cudaGetSymbolAddress((void**)&pal, g_al);

    size_t gsmem = (size_t)(2 * GBUF) * sizeof(unsigned);
    cudaFuncSetAttribute(gemm_qkv_kernel,
                         cudaFuncAttributeMaxDynamicSharedMemorySize, (int)gsmem);
    cudaFuncSetAttribute(gemm_o_kernel,
                         cudaFuncAttributeMaxDynamicSharedMemorySize, (int)gsmem);

    // presplit x
    presplit_kernel<<<(S_LEN * HIDDEN / 2) / 256, 256>>>(x, pxh, pxl);

    // fused QKV projection
    {
        dim3 grid(48, S_LEN / BM);
        gemm_qkv_kernel<<<grid, 256, gsmem>>>(
            pxh, pxl,
            q_qweight, q_scales, q_qzeros, q_bias,
            k_qweight, k_scales, k_qzeros, k_bias,
            v_qweight, v_scales, v_qzeros, v_bias,
            pq, pk, pv);
    }

    // RoPE (Q in-place) + K/V presplit
    {
        dim3 grid(12, S_LEN);
        rope_split_kernel<<<grid, 256>>>(pq, pk, pv, pkh, pkl, pvh, pvl, cosb, sinb);
    }

    // Flash attention (64-row tiles, 128-thread CTAs, 2 CTAs/SM)
    {
        size_t smem = (size_t)(4 * FPLANE) * sizeof(unsigned);   // 69632 B
        cudaFuncSetAttribute(flash_tc_kernel,
                             cudaFuncAttributeMaxDynamicSharedMemorySize, (int)smem);
        dim3 grid(S_LEN / FBQ, NH);
        flash_tc_kernel<<<grid, FTHREADS, smem>>>(pq, pkh, pkl, pvh, pvl, pah, pal);
    }

    // O projection
    {
        dim3 grid(HIDDEN / BN, S_LEN / BM);
        gemm_o_kernel<<<grid, 256, gsmem>>>(pah, pal, o_qweight, o_scales, o_qzeros, out);
    }
}